// round 11
// baseline (speedup 1.0000x reference)
#include <cuda_runtime.h>
#include <cuda_fp16.h>
#include <math.h>
#include <stdint.h>

// ---------------- problem constants ------------------------------------------
#define NN      20000
#define TT      60
#define DDIM    20
#define HH      128
#define GGDIM   128
#define NHEADS  4
#define CCH     32
#define EE      320000
#define ETOT    (EE + NN)
#define G4      512
#define LNODES  144
#define MTILES  9
#define LGRID   139
#define GSTR    (LGRID * LNODES)
#define LTHR    512

#define KXP     40
#define KHP     136
#define AXE     (LNODES * DDIM)

// ---------------- LSTM smem layout (bytes) -----------------------------------
#define OFF_AH1  0
#define OFF_WX   0
#define OFF_WH   40960
#define OFF_AX   172032
#define OFF_AH0  183552
#define OFF_BIAS 222720
#define SMEM_TOTAL 224768

// ---------------- GAT gemm+attn smem layout (bytes, dynamic) ------------------
#define GOFF_A   0
#define GOFF_B   16384
#define GOFF_AS  49152
#define GOFF_AD  49664
#define GSMEM    50176

// ---------------- scratch (device globals) ------------------------------------
__device__ float g_h[GSTR * HH];
__device__ float g_xh[NN * GGDIM];
__device__ float g_feat[NN * GGDIM];
__device__ float g_asr[NN * NHEADS];
__device__ float g_adt[NN * NHEADS];
__device__ int   g_cnt[NN];          // loader-zeroed; re-zeroed by scan each call
__device__ int   g_row[NN + 1];
__device__ int   g_cur[NN];
__device__ int   g_csr[ETOT];

// ---------------- helpers -----------------------------------------------------
__device__ __forceinline__ __half2 tanh2h(__half2 x) {
    uint32_t xi = *(uint32_t*)&x, yi;
    asm("tanh.approx.f16x2 %0, %1;" : "=r"(yi) : "r"(xi));
    return *(__half2*)&yi;
}
__device__ __forceinline__ void mma16816(float* d,
                                         uint32_t a0, uint32_t a1, uint32_t a2, uint32_t a3,
                                         uint32_t b0, uint32_t b1) {
    asm volatile(
        "mma.sync.aligned.m16n8k16.row.col.f32.f16.f16.f32 "
        "{%0,%1,%2,%3}, {%4,%5,%6,%7}, {%8,%9}, {%0,%1,%2,%3};"
        : "+f"(d[0]), "+f"(d[1]), "+f"(d[2]), "+f"(d[3])
        : "r"(a0), "r"(a1), "r"(a2), "r"(a3), "r"(b0), "r"(b1));
}
__device__ __forceinline__ void ldm_x4(uint32_t addr, uint32_t* r) {
    asm volatile("ldmatrix.sync.aligned.m8n8.x4.shared.b16 {%0,%1,%2,%3}, [%4];"
                 : "=r"(r[0]), "=r"(r[1]), "=r"(r[2]), "=r"(r[3]) : "r"(addr));
}
__device__ __forceinline__ float lrelu(float v) { return v > 0.0f ? v : 0.2f * v; }

// ---------------- persistent LSTM kernel (f16x2 MUFU epilogue) ----------------
__global__ __launch_bounds__(LTHR, 1) void lstm_all_kernel(
    const float* __restrict__ x,
    const float* __restrict__ Wih, const float* __restrict__ Whh,
    const float* __restrict__ bih, const float* __restrict__ bhh)
{
    extern __shared__ char smem[];
    __half* WX = (__half*)(smem + OFF_WX);
    __half* AX = (__half*)(smem + OFF_AX);
    float*  sbias = (float*)(smem + OFF_BIAS);
    const uint32_t sWX  = (uint32_t)__cvta_generic_to_shared(smem + OFF_WX);
    const uint32_t sWH  = (uint32_t)__cvta_generic_to_shared(smem + OFF_WH);
    const uint32_t sAX  = (uint32_t)__cvta_generic_to_shared(smem + OFF_AX);
    const uint32_t sAH0 = (uint32_t)__cvta_generic_to_shared(smem + OFF_AH0);
    const uint32_t sAH1 = (uint32_t)__cvta_generic_to_shared(smem + OFF_AH1);

    const int tid = threadIdx.x;
    const int blk = blockIdx.x;

    for (int i = tid; i < OFF_BIAS / 4; i += LTHR) ((uint32_t*)smem)[i] = 0;
    __syncthreads();

    for (int i = tid; i < G4 * DDIM; i += LTHR) {
        int n = i / DDIM, k = i - n * DDIM;
        int row = (n & 3) * HH + (n >> 2);
        WX[n * KXP + k] = __float2half_rn(Wih[row * DDIM + k]);
    }
    for (int i = tid; i < G4 * HH; i += LTHR) {
        int n = i >> 7, k = i & 127;
        int row = (n & 3) * HH + (n >> 2);
        uint32_t byte = (uint32_t)(n * 256 + ((((k >> 3) ^ (n & 7)) << 4)) + ((k & 7) << 1));
        *(__half*)(smem + OFF_WH + byte) = __float2half_rn(Whh[row * HH + k]);
    }
    for (int i = tid; i < G4; i += LTHR) {
        int row = (i & 3) * HH + (i >> 2);
        sbias[i] = bih[row] + bhh[row];
    }
    __syncthreads();

    const int wid  = tid >> 5;
    const int lane = tid & 31;
    const int g    = lane >> 2;
    const int cc   = lane & 3;
    const int n0   = wid * 32;
    const bool odd = (lane & 1);
    const int jbase = (n0 >> 2) + (cc >> 1);

    const int sub = lane >> 3, rr = lane & 7;
    const int arow = (sub & 1) * 8 + rr;
    const int akof = (sub >> 1) * 8;
    const int bcol = rr + ((sub >> 1) * 8);
    const int bkof = (sub & 1) * 8;
    const uint32_t laneAH = (uint32_t)(arow * KHP + akof) * 2;
    const uint32_t axb  = sAX  + (uint32_t)(arow * KXP + akof) * 2;
    const uint32_t ahb0 = sAH0 + laneAH;
    const uint32_t ahb1 = sAH1 + laneAH;
    const uint32_t xorv = (uint32_t)(rr << 4);
    uint32_t wxb[2], whb[2];
#pragma unroll
    for (int np = 0; np < 2; ++np) {
        wxb[np] = sWX + (uint32_t)((n0 + np * 16 + bcol) * KXP + bkof) * 2;
        whb[np] = sWH + (uint32_t)(n0 + np * 16 + bcol) * 256;
    }
    const uint32_t bko2 = (uint32_t)(bkof << 1);

    float bias0[4], bias1[4];
#pragma unroll
    for (int nt = 0; nt < 4; ++nt) {
        bias0[nt] = sbias[n0 + nt * 8 + 2 * cc];
        bias1[nt] = sbias[n0 + nt * 8 + 2 * cc + 1];
    }

    uint32_t bxf[2][2][4];
#pragma unroll
    for (int ks = 0; ks < 2; ++ks)
#pragma unroll
        for (int np = 0; np < 2; ++np)
            ldm_x4(wxb[np] + (uint32_t)(ks * 32), bxf[ks][np]);

    float creg[MTILES][4];
#pragma unroll
    for (int mt = 0; mt < MTILES; ++mt)
#pragma unroll
        for (int nt = 0; nt < 4; ++nt) creg[mt][nt] = 0.0f;

    __syncthreads();

    for (int s = 0; s < TT; ++s) {
        for (int i = tid; i < AXE; i += LTHR) {
            int mm = i / DDIM, k = i - mm * DDIM;
            int n = blk * LNODES + mm;
            AX[mm * KXP + k] = __float2half_rn(n < NN ? x[n * (TT * DDIM) + s * DDIM + k] : 0.0f);
        }
        __syncthreads();

        const bool last = (s == TT - 1);
        const uint32_t ahb_r = (s & 1) ? ahb1 : ahb0;
        __half* AHW = (__half*)(smem + ((s & 1) ? OFF_AH0 : OFF_AH1));

        auto epilogue = [&](int mt, float (&acc)[4][4]) {
            const int row = (!odd) ? (mt * 16 + g) : (mt * 16 + g + 8);
#pragma unroll
            for (int nt = 0; nt < 4; nt += 2) {
                float gia, gfa, gga, goa, gib, gfb, ggb, gob;
#pragma unroll
                for (int q = 0; q < 2; ++q) {
                    float c0 = acc[nt + q][0], c1 = acc[nt + q][1];
                    float c2 = acc[nt + q][2], c3 = acc[nt + q][3];
                    float x0 = __shfl_xor_sync(0xffffffffu, c0, 1);
                    float x1 = __shfl_xor_sync(0xffffffffu, c1, 1);
                    float x2 = __shfl_xor_sync(0xffffffffu, c2, 1);
                    float x3 = __shfl_xor_sync(0xffffffffu, c3, 1);
                    float gi, gf, gg, go;
                    if (!odd) { gi = c0; gf = c1; gg = x0; go = x1; }
                    else      { gi = x2; gf = x3; gg = c2; go = c3; }
                    if (q == 0) { gia = gi; gfa = gf; gga = gg; goa = go; }
                    else        { gib = gi; gfb = gf; ggb = gg; gob = go; }
                }
                // paired f16x2 MUFU: 5 ops for 2 cells (was 10)
                __half2 tA = tanh2h(__floats2half2_rn(0.5f * gia, 0.5f * gfa));
                __half2 tB = tanh2h(__floats2half2_rn(0.5f * gib, 0.5f * gfb));
                __half2 tG = tanh2h(__floats2half2_rn(gga, ggb));
                __half2 tO = tanh2h(__floats2half2_rn(0.5f * goa, 0.5f * gob));
                float sia = fmaf(__low2float(tA),  0.5f, 0.5f);
                float sfa = fmaf(__high2float(tA), 0.5f, 0.5f);
                float sib = fmaf(__low2float(tB),  0.5f, 0.5f);
                float sfb = fmaf(__high2float(tB), 0.5f, 0.5f);
                float soa = fmaf(__low2float(tO),  0.5f, 0.5f);
                float sob = fmaf(__high2float(tO), 0.5f, 0.5f);
                float cna = sfa * creg[mt][nt]     + sia * __low2float(tG);
                float cnb = sfb * creg[mt][nt + 1] + sib * __high2float(tG);
                creg[mt][nt]     = cna;
                creg[mt][nt + 1] = cnb;
                __half2 tC = tanh2h(__floats2half2_rn(cna, cnb));
                float hva = soa * __low2float(tC);
                float hvb = sob * __high2float(tC);
                int ja = jbase + nt * 2, jb = ja + 2;
                AHW[row * KHP + ja] = __float2half_rn(hva);
                AHW[row * KHP + jb] = __float2half_rn(hvb);
                if (last) {
                    g_h[(blk * LNODES + row) * HH + ja] = hva;
                    g_h[(blk * LNODES + row) * HH + jb] = hvb;
                }
            }
        };

#pragma unroll
        for (int p = 0; p < 5; ++p) {
            const int m0 = 2 * p;
            const bool has1 = (m0 + 1 < MTILES);

            float acc0[4][4], acc1[4][4];
#pragma unroll
            for (int nt = 0; nt < 4; ++nt) {
                acc0[nt][0] = bias0[nt]; acc0[nt][1] = bias1[nt];
                acc0[nt][2] = bias0[nt]; acc0[nt][3] = bias1[nt];
                acc1[nt][0] = bias0[nt]; acc1[nt][1] = bias1[nt];
                acc1[nt][2] = bias0[nt]; acc1[nt][3] = bias1[nt];
            }
#pragma unroll
            for (int ks = 0; ks < 2; ++ks) {
                uint32_t a[4];
                ldm_x4(axb + (uint32_t)(m0 * 16 * (KXP * 2) + ks * 32), a);
#pragma unroll
                for (int np = 0; np < 2; ++np) {
                    mma16816(acc0[2 * np],     a[0], a[1], a[2], a[3], bxf[ks][np][0], bxf[ks][np][1]);
                    mma16816(acc0[2 * np + 1], a[0], a[1], a[2], a[3], bxf[ks][np][2], bxf[ks][np][3]);
                }
                if (has1) {
                    uint32_t a1[4];
                    ldm_x4(axb + (uint32_t)((m0 + 1) * 16 * (KXP * 2) + ks * 32), a1);
#pragma unroll
                    for (int np = 0; np < 2; ++np) {
                        mma16816(acc1[2 * np],     a1[0], a1[1], a1[2], a1[3], bxf[ks][np][0], bxf[ks][np][1]);
                        mma16816(acc1[2 * np + 1], a1[0], a1[1], a1[2], a1[3], bxf[ks][np][2], bxf[ks][np][3]);
                    }
                }
            }
#pragma unroll
            for (int ks = 0; ks < 8; ++ks) {
                uint32_t b0[4], b1[4];
                ldm_x4(whb[0] + (((uint32_t)(ks * 32) + bko2) ^ xorv), b0);
                ldm_x4(whb[1] + (((uint32_t)(ks * 32) + bko2) ^ xorv), b1);
                uint32_t a[4];
                ldm_x4(ahb_r + (uint32_t)(m0 * 16 * (KHP * 2) + ks * 32), a);
                mma16816(acc0[0], a[0], a[1], a[2], a[3], b0[0], b0[1]);
                mma16816(acc0[1], a[0], a[1], a[2], a[3], b0[2], b0[3]);
                mma16816(acc0[2], a[0], a[1], a[2], a[3], b1[0], b1[1]);
                mma16816(acc0[3], a[0], a[1], a[2], a[3], b1[2], b1[3]);
                if (has1) {
                    uint32_t a1[4];
                    ldm_x4(ahb_r + (uint32_t)((m0 + 1) * 16 * (KHP * 2) + ks * 32), a1);
                    mma16816(acc1[0], a1[0], a1[1], a1[2], a1[3], b0[0], b0[1]);
                    mma16816(acc1[1], a1[0], a1[1], a1[2], a1[3], b0[2], b0[3]);
                    mma16816(acc1[2], a1[0], a1[1], a1[2], a1[3], b1[0], b1[1]);
                    mma16816(acc1[3], a1[0], a1[1], a1[2], a1[3], b1[2], b1[3]);
                }
            }

            epilogue(m0, acc0);
            if (has1) epilogue(m0 + 1, acc1);
        }
        __syncthreads();
    }
}

// ---------------- CSR build ----------------------------------------------------
__global__ void csr_count_kernel(const int* __restrict__ ei) {
    int e = blockIdx.x * blockDim.x + threadIdx.x;
    if (e >= ETOT) return;
    int d = (e < EE) ? ei[EE + e] : (e - EE);
    atomicAdd(&g_cnt[d], 1);
}
__global__ __launch_bounds__(1024) void csr_scan_kernel() {
    __shared__ int swarp[32];
    const int t = threadIdx.x;
    const int lane = t & 31, wid = t >> 5;
    const int ITEMS = (NN + 1023) / 1024;
    const int base = t * ITEMS;

    int c[ITEMS];
    int total = 0;
#pragma unroll
    for (int i = 0; i < ITEMS; ++i) {
        int idx = base + i;
        c[i] = (idx < NN) ? g_cnt[idx] : 0;
        total += c[i];
        if (idx < NN) g_cnt[idx] = 0;
    }
    int incl = total;
#pragma unroll
    for (int o = 1; o < 32; o <<= 1) {
        int v = __shfl_up_sync(0xffffffffu, incl, o);
        if (lane >= o) incl += v;
    }
    if (lane == 31) swarp[wid] = incl;
    __syncthreads();
    if (wid == 0) {
        int w = swarp[lane];
        int wi = w;
#pragma unroll
        for (int o = 1; o < 32; o <<= 1) {
            int v = __shfl_up_sync(0xffffffffu, wi, o);
            if (lane >= o) wi += v;
        }
        swarp[lane] = wi - w;
    }
    __syncthreads();
    int run = swarp[wid] + (incl - total);
#pragma unroll
    for (int i = 0; i < ITEMS; ++i) {
        int idx = base + i;
        if (idx < NN) {
            g_row[idx] = run;
            g_cur[idx] = run;
            run += c[i];
        }
    }
    if (t == 1023) g_row[NN] = run;
}
__global__ void csr_scatter_kernel(const int* __restrict__ ei) {
    int e = blockIdx.x * blockDim.x + threadIdx.x;
    if (e >= ETOT) return;
    int s, d;
    if (e < EE) { s = ei[e]; d = ei[EE + e]; } else { s = e - EE; d = s; }
    int pos = atomicAdd(&g_cur[d], 1);
    g_csr[pos] = s;
}

// ---------------- fused GAT dense: xh = X@W (HMMA) + attn dots ----------------
__global__ __launch_bounds__(128) void gat_gemm_attn_kernel(
    const float* __restrict__ W, const float* __restrict__ a_src,
    const float* __restrict__ a_dst, int layer)
{
    const float* __restrict__ X = (layer == 0) ? g_h : g_feat;
    extern __shared__ char smem[];
    float* sas = (float*)(smem + GOFF_AS);
    float* sad = (float*)(smem + GOFF_AD);
    const uint32_t sA = (uint32_t)__cvta_generic_to_shared(smem + GOFF_A);
    const uint32_t sB = (uint32_t)__cvta_generic_to_shared(smem + GOFF_B);

    const int tid = threadIdx.x;
    const int n64 = blockIdx.x * 64;

    for (int i = tid; i < 64 * 128; i += 128) {
        int r = i >> 7, k = i & 127;
        float v = (n64 + r < NN) ? X[(n64 + r) * GGDIM + k] : 0.0f;
        uint32_t byte = (uint32_t)(r * 256 + (((k >> 3) ^ (r & 7)) << 4) + ((k & 7) << 1));
        *(__half*)(smem + GOFF_A + byte) = __float2half_rn(v);
    }
    for (int i = tid; i < 128 * 128; i += 128) {
        int n = i >> 7, k = i & 127;
        uint32_t byte = (uint32_t)(n * 256 + (((k >> 3) ^ (n & 7)) << 4) + ((k & 7) << 1));
        *(__half*)(smem + GOFF_B + byte) = __float2half_rn(W[k * GGDIM + n]);
    }
    if (tid < 128) { sas[tid] = a_src[tid]; sad[tid] = a_dst[tid]; }
    __syncthreads();

    const int wid  = tid >> 5;
    const int lane = tid & 31;
    const int g    = lane >> 2;
    const int cc   = lane & 3;
    const int sub = lane >> 3, rr = lane & 7;
    const int arow = (sub & 1) * 8 + rr;
    const int akof = (sub >> 1) * 8;
    const int bcol = rr + ((sub >> 1) * 8);
    const int bkof = (sub & 1) * 8;
    const uint32_t xorv = (uint32_t)(rr << 4);
    const uint32_t ako2 = (uint32_t)(akof << 1);
    const uint32_t bko2 = (uint32_t)(bkof << 1);
    const uint32_t arowb = sA + (uint32_t)(wid * 16 + arow) * 256;

    float acc[16][4];
#pragma unroll
    for (int q = 0; q < 16; ++q)
#pragma unroll
        for (int z = 0; z < 4; ++z) acc[q][z] = 0.0f;

#pragma unroll
    for (int ks = 0; ks < 8; ++ks) {
        uint32_t a[4];
        ldm_x4(arowb + (((uint32_t)(ks * 32) + ako2) ^ xorv), a);
#pragma unroll
        for (int np = 0; np < 8; ++np) {
            uint32_t b[4];
            ldm_x4(sB + (uint32_t)(np * 16 + bcol) * 256 + (((uint32_t)(ks * 32) + bko2) ^ xorv), b);
            mma16816(acc[2 * np],     a[0], a[1], a[2], a[3], b[0], b[1]);
            mma16816(acc[2 * np + 1], a[0], a[1], a[2], a[3], b[2], b[3]);
        }
    }

    const int gr0 = n64 + wid * 16 + g;
    const int gr1 = gr0 + 8;
#pragma unroll
    for (int np = 0; np < 8; ++np) {
        int c0 = np * 16 + 2 * cc, c1 = np * 16 + 8 + 2 * cc;
        if (gr0 < NN) {
            *(float2*)&g_xh[gr0 * GGDIM + c0] = make_float2(acc[2 * np][0], acc[2 * np][1]);
            *(float2*)&g_xh[gr0 * GGDIM + c1] = make_float2(acc[2 * np + 1][0], acc[2 * np + 1][1]);
        }
        if (gr1 < NN) {
            *(float2*)&g_xh[gr1 * GGDIM + c0] = make_float2(acc[2 * np][2], acc[2 * np][3]);
            *(float2*)&g_xh[gr1 * GGDIM + c1] = make_float2(acc[2 * np + 1][2], acc[2 * np + 1][3]);
        }
    }

    float rs0[4], rs1[4], rd0[4], rd1[4];
#pragma unroll
    for (int h = 0; h < 4; ++h) {
        float s0 = 0.0f, s1 = 0.0f, d0 = 0.0f, d1 = 0.0f;
#pragma unroll
        for (int tti = 0; tti < 4; ++tti) {
            int np = h * 2 + (tti >> 1);
            int ai = 2 * np + (tti & 1);
            int col = np * 16 + (tti & 1) * 8 + 2 * cc;
            float w0s = sas[col], w1s = sas[col + 1];
            float w0d = sad[col], w1d = sad[col + 1];
            s0 += acc[ai][0] * w0s + acc[ai][1] * w1s;
            s1 += acc[ai][2] * w0s + acc[ai][3] * w1s;
            d0 += acc[ai][0] * w0d + acc[ai][1] * w1d;
            d1 += acc[ai][2] * w0d + acc[ai][3] * w1d;
        }
        s0 += __shfl_xor_sync(0xffffffffu, s0, 1); s0 += __shfl_xor_sync(0xffffffffu, s0, 2);
        s1 += __shfl_xor_sync(0xffffffffu, s1, 1); s1 += __shfl_xor_sync(0xffffffffu, s1, 2);
        d0 += __shfl_xor_sync(0xffffffffu, d0, 1); d0 += __shfl_xor_sync(0xffffffffu, d0, 2);
        d1 += __shfl_xor_sync(0xffffffffu, d1, 1); d1 += __shfl_xor_sync(0xffffffffu, d1, 2);
        rs0[h] = s0; rs1[h] = s1; rd0[h] = d0; rd1[h] = d1;
    }
    if (gr0 < NN) { g_asr[gr0 * 4 + cc] = rs0[cc]; g_adt[gr0 * 4 + cc] = rd0[cc]; }
    if (gr1 < NN) { g_asr[gr1 * 4 + cc] = rs1[cc]; g_adt[gr1 * 4 + cc] = rd1[cc]; }
}

// -------- fused softmax + aggregate + bias + ELU (+ optional head) ------------
__global__ __launch_bounds__(256) void gat_agg_kernel(
    const float* __restrict__ bias, const float* __restrict__ Wh,
    const float* __restrict__ bh, float* __restrict__ out, int last)
{
    const int d    = (blockIdx.x * 256 + threadIdx.x) >> 5;
    const int lane = threadIdx.x & 31;
    if (d >= NN) return;
    const int start = g_row[d], end = g_row[d + 1];

    const float4 adt4 = *(const float4*)&g_adt[d * 4];

    float s0 = 0.0f, s1 = 0.0f, s2 = 0.0f, s3 = 0.0f;
    for (int idx = start + lane; idx < end; idx += 32) {
        int s = g_csr[idx];
        float4 a = *(const float4*)&g_asr[s * 4];
        s0 += __expf(lrelu(a.x + adt4.x));
        s1 += __expf(lrelu(a.y + adt4.y));
        s2 += __expf(lrelu(a.z + adt4.z));
        s3 += __expf(lrelu(a.w + adt4.w));
    }
#pragma unroll
    for (int off = 16; off > 0; off >>= 1) {
        s0 += __shfl_xor_sync(0xffffffffu, s0, off);
        s1 += __shfl_xor_sync(0xffffffffu, s1, off);
        s2 += __shfl_xor_sync(0xffffffffu, s2, off);
        s3 += __shfl_xor_sync(0xffffffffu, s3, off);
    }

    const int head = lane >> 3;
    float adt_h, den_h;
    if (head == 0)      { adt_h = adt4.x; den_h = s0; }
    else if (head == 1) { adt_h = adt4.y; den_h = s1; }
    else if (head == 2) { adt_h = adt4.z; den_h = s2; }
    else                { adt_h = adt4.w; den_h = s3; }
    const float inv_den = 1.0f / (den_h + 1e-16f);

    float4 acc = make_float4(0.0f, 0.0f, 0.0f, 0.0f);
    for (int idx = start; idx < end; ++idx) {
        int s = g_csr[idx];
        float as_h = g_asr[s * 4 + head];
        float alpha = __expf(lrelu(as_h + adt_h)) * inv_den;
        float4 xv = *(const float4*)&g_xh[s * GGDIM + lane * 4];
        acc.x = fmaf(alpha, xv.x, acc.x);
        acc.y = fmaf(alpha, xv.y, acc.y);
        acc.z = fmaf(alpha, xv.z, acc.z);
        acc.w = fmaf(alpha, xv.w, acc.w);
    }

    const float4 bv = *(const float4*)&bias[lane * 4];
    float4 outv;
    float v;
    v = acc.x + bv.x; outv.x = v > 0.0f ? v : (__expf(v) - 1.0f);
    v = acc.y + bv.y; outv.y = v > 0.0f ? v : (__expf(v) - 1.0f);
    v = acc.z + bv.z; outv.z = v > 0.0f ? v : (__expf(v) - 1.0f);
    v = acc.w + bv.w; outv.w = v > 0.0f ? v : (__expf(v) - 1.0f);

    if (!last) {
        *(float4*)&g_feat[d * GGDIM + lane * 4] = outv;
    } else {
        int ch = lane * 4;
        float p0 = outv.x * Wh[2 * ch + 0] + outv.y * Wh[2 * ch + 2]
                 + outv.z * Wh[2 * ch + 4] + outv.w * Wh[2 * ch + 6];
        float p1 = outv.x * Wh[2 * ch + 1] + outv.y * Wh[2 * ch + 3]
                 + outv.z * Wh[2 * ch + 5] + outv.w * Wh[2 * ch + 7];
#pragma unroll
        for (int off = 16; off > 0; off >>= 1) {
            p0 += __shfl_xor_sync(0xffffffffu, p0, off);
            p1 += __shfl_xor_sync(0xffffffffu, p1, off);
        }
        if (lane == 0) {
            out[2 * d + 0] = p0 + bh[0];
            out[2 * d + 1] = p1 + bh[1];
        }
    }
}

// ---------------- launch --------------------------------------------------------
extern "C" void kernel_launch(void* const* d_in, const int* in_sizes, int n_in,
                              void* d_out, int out_size) {
    const float* x_win  = (const float*)d_in[0];
    const int*   ei     = (const int*)  d_in[1];
    const float* Wih    = (const float*)d_in[2];
    const float* Whh    = (const float*)d_in[3];
    const float* bih    = (const float*)d_in[4];
    const float* bhh    = (const float*)d_in[5];
    const float* W1     = (const float*)d_in[6];
    const float* asrc1  = (const float*)d_in[7];
    const float* adst1  = (const float*)d_in[8];
    const float* b1     = (const float*)d_in[9];
    const float* W2     = (const float*)d_in[10];
    const float* asrc2  = (const float*)d_in[11];
    const float* adst2  = (const float*)d_in[12];
    const float* b2     = (const float*)d_in[13];
    const float* Wh     = (const float*)d_in[14];
    const float* bh     = (const float*)d_in[15];
    float* out = (float*)d_out;

    cudaFuncSetAttribute(lstm_all_kernel,
                         cudaFuncAttributeMaxDynamicSharedMemorySize, SMEM_TOTAL);
    cudaFuncSetAttribute(gat_gemm_attn_kernel,
                         cudaFuncAttributeMaxDynamicSharedMemorySize, GSMEM);

    lstm_all_kernel<<<LGRID, LTHR, SMEM_TOTAL>>>(x_win, Wih, Whh, bih, bhh);

    csr_count_kernel<<<(ETOT + 255) / 256, 256>>>(ei);
    csr_scan_kernel<<<1, 1024>>>();
    csr_scatter_kernel<<<(ETOT + 255) / 256, 256>>>(ei);

    for (int layer = 0; layer < 2; layer++) {
        const float* W    = layer ? W2    : W1;
        const float* asrc = layer ? asrc2 : asrc1;
        const float* adst = layer ? adst2 : adst1;
        const float* bb   = layer ? b2    : b1;

        gat_gemm_attn_kernel<<<(NN + 63) / 64, 128, GSMEM>>>(W, asrc, adst, layer);
        gat_agg_kernel<<<(NN * 32 + 255) / 256, 256>>>(bb, Wh, bh, out, layer);
    }
}

// round 12
// speedup vs baseline: 1.0132x; 1.0132x over previous
#include <cuda_runtime.h>
#include <cuda_fp16.h>
#include <math.h>
#include <stdint.h>

// ---------------- problem constants ------------------------------------------
#define NN      20000
#define TT      60
#define DDIM    20
#define HH      128
#define GGDIM   128
#define NHEADS  4
#define CCH     32
#define EE      320000
#define ETOT    (EE + NN)
#define G4      512
#define LNODES  144
#define MTILES  9
#define LGRID   139
#define GSTR    (LGRID * LNODES)
#define LTHR    512

#define KXP     40
#define KHP     136
#define AXE     (LNODES * DDIM)

// ---------------- LSTM smem layout (bytes) -----------------------------------
#define OFF_AH1  0
#define OFF_WX   0
#define OFF_WH   40960
#define OFF_AX   172032
#define OFF_AH0  183552
#define OFF_BIAS 222720
#define SMEM_TOTAL 224768

// ---------------- GAT gemm+attn smem layout (bytes, dynamic) ------------------
#define GOFF_A   0
#define GOFF_B   16384
#define GOFF_AS  49152
#define GOFF_AD  49664
#define GSMEM    50176

// ---------------- scratch (device globals) ------------------------------------
__device__ float g_h[GSTR * HH];
__device__ float g_xh[NN * GGDIM];
__device__ float g_feat[NN * GGDIM];
__device__ float g_asr[NN * NHEADS];
__device__ float g_adt[NN * NHEADS];
__device__ int   g_cnt[NN];          // loader-zeroed; re-zeroed by scan each call
__device__ int   g_row[NN + 1];
__device__ int   g_cur[NN];
__device__ int   g_csr[ETOT];

// ---------------- helpers -----------------------------------------------------
__device__ __forceinline__ float tanhapx(float x) {
    float y; asm("tanh.approx.f32 %0, %1;" : "=f"(y) : "f"(x)); return y;
}
__device__ __forceinline__ float sigt(float x) {
    return fmaf(tanhapx(0.5f * x), 0.5f, 0.5f);
}
__device__ __forceinline__ void mma16816(float* d,
                                         uint32_t a0, uint32_t a1, uint32_t a2, uint32_t a3,
                                         uint32_t b0, uint32_t b1) {
    asm volatile(
        "mma.sync.aligned.m16n8k16.row.col.f32.f16.f16.f32 "
        "{%0,%1,%2,%3}, {%4,%5,%6,%7}, {%8,%9}, {%0,%1,%2,%3};"
        : "+f"(d[0]), "+f"(d[1]), "+f"(d[2]), "+f"(d[3])
        : "r"(a0), "r"(a1), "r"(a2), "r"(a3), "r"(b0), "r"(b1));
}
__device__ __forceinline__ void ldm_x4(uint32_t addr, uint32_t* r) {
    asm volatile("ldmatrix.sync.aligned.m8n8.x4.shared.b16 {%0,%1,%2,%3}, [%4];"
                 : "=r"(r[0]), "=r"(r[1]), "=r"(r[2]), "=r"(r[3]) : "r"(addr));
}
__device__ __forceinline__ float lrelu(float v) { return v > 0.0f ? v : 0.2f * v; }

// ---------------- persistent LSTM kernel (m-tile triples, scalar epilogue) ----
__global__ __launch_bounds__(LTHR, 1) void lstm_all_kernel(
    const float* __restrict__ x,
    const float* __restrict__ Wih, const float* __restrict__ Whh,
    const float* __restrict__ bih, const float* __restrict__ bhh)
{
    extern __shared__ char smem[];
    __half* WX = (__half*)(smem + OFF_WX);
    __half* AX = (__half*)(smem + OFF_AX);
    float*  sbias = (float*)(smem + OFF_BIAS);
    const uint32_t sWX  = (uint32_t)__cvta_generic_to_shared(smem + OFF_WX);
    const uint32_t sWH  = (uint32_t)__cvta_generic_to_shared(smem + OFF_WH);
    const uint32_t sAX  = (uint32_t)__cvta_generic_to_shared(smem + OFF_AX);
    const uint32_t sAH0 = (uint32_t)__cvta_generic_to_shared(smem + OFF_AH0);
    const uint32_t sAH1 = (uint32_t)__cvta_generic_to_shared(smem + OFF_AH1);

    const int tid = threadIdx.x;
    const int blk = blockIdx.x;

    for (int i = tid; i < OFF_BIAS / 4; i += LTHR) ((uint32_t*)smem)[i] = 0;
    __syncthreads();

    for (int i = tid; i < G4 * DDIM; i += LTHR) {
        int n = i / DDIM, k = i - n * DDIM;
        int row = (n & 3) * HH + (n >> 2);
        WX[n * KXP + k] = __float2half_rn(Wih[row * DDIM + k]);
    }
    for (int i = tid; i < G4 * HH; i += LTHR) {
        int n = i >> 7, k = i & 127;
        int row = (n & 3) * HH + (n >> 2);
        uint32_t byte = (uint32_t)(n * 256 + ((((k >> 3) ^ (n & 7)) << 4)) + ((k & 7) << 1));
        *(__half*)(smem + OFF_WH + byte) = __float2half_rn(Whh[row * HH + k]);
    }
    for (int i = tid; i < G4; i += LTHR) {
        int row = (i & 3) * HH + (i >> 2);
        sbias[i] = bih[row] + bhh[row];
    }
    __syncthreads();

    const int wid  = tid >> 5;
    const int lane = tid & 31;
    const int g    = lane >> 2;
    const int cc   = lane & 3;
    const int n0   = wid * 32;
    const bool odd = (lane & 1);
    const int jbase = (n0 >> 2) + (cc >> 1);

    const int sub = lane >> 3, rr = lane & 7;
    const int arow = (sub & 1) * 8 + rr;
    const int akof = (sub >> 1) * 8;
    const int bcol = rr + ((sub >> 1) * 8);
    const int bkof = (sub & 1) * 8;
    const uint32_t laneAH = (uint32_t)(arow * KHP + akof) * 2;
    const uint32_t axb  = sAX  + (uint32_t)(arow * KXP + akof) * 2;
    const uint32_t ahb0 = sAH0 + laneAH;
    const uint32_t ahb1 = sAH1 + laneAH;
    const uint32_t xorv = (uint32_t)(rr << 4);
    uint32_t wxb[2], whb[2];
#pragma unroll
    for (int np = 0; np < 2; ++np) {
        wxb[np] = sWX + (uint32_t)((n0 + np * 16 + bcol) * KXP + bkof) * 2;
        whb[np] = sWH + (uint32_t)(n0 + np * 16 + bcol) * 256;
    }
    const uint32_t bko2 = (uint32_t)(bkof << 1);

    float bias0[4], bias1[4];
#pragma unroll
    for (int nt = 0; nt < 4; ++nt) {
        bias0[nt] = sbias[n0 + nt * 8 + 2 * cc];
        bias1[nt] = sbias[n0 + nt * 8 + 2 * cc + 1];
    }

    uint32_t bxf[2][2][4];
#pragma unroll
    for (int ks = 0; ks < 2; ++ks)
#pragma unroll
        for (int np = 0; np < 2; ++np)
            ldm_x4(wxb[np] + (uint32_t)(ks * 32), bxf[ks][np]);

    float creg[MTILES][4];
#pragma unroll
    for (int mt = 0; mt < MTILES; ++mt)
#pragma unroll
        for (int nt = 0; nt < 4; ++nt) creg[mt][nt] = 0.0f;

    __syncthreads();

    for (int s = 0; s < TT; ++s) {
        for (int i = tid; i < AXE; i += LTHR) {
            int mm = i / DDIM, k = i - mm * DDIM;
            int n = blk * LNODES + mm;
            AX[mm * KXP + k] = __float2half_rn(n < NN ? x[n * (TT * DDIM) + s * DDIM + k] : 0.0f);
        }
        __syncthreads();

        const bool last = (s == TT - 1);
        const uint32_t ahb_r = (s & 1) ? ahb1 : ahb0;
        __half* AHW = (__half*)(smem + ((s & 1) ? OFF_AH0 : OFF_AH1));

        auto epilogue = [&](int mt, float (&acc)[4][4]) {
#pragma unroll
            for (int nt = 0; nt < 4; ++nt) {
                float c0 = acc[nt][0], c1 = acc[nt][1], c2 = acc[nt][2], c3 = acc[nt][3];
                float x0 = __shfl_xor_sync(0xffffffffu, c0, 1);
                float x1 = __shfl_xor_sync(0xffffffffu, c1, 1);
                float x2 = __shfl_xor_sync(0xffffffffu, c2, 1);
                float x3 = __shfl_xor_sync(0xffffffffu, c3, 1);
                float gi, gf, gg, go; int row;
                if (!odd) { gi = c0; gf = c1; gg = x0; go = x1; row = mt * 16 + g; }
                else      { gi = x2; gf = x3; gg = c2; go = c3; row = mt * 16 + g + 8; }
                int j = jbase + nt * 2;
                float cold = creg[mt][nt];
                float cn = sigt(gf) * cold + sigt(gi) * tanhapx(gg);
                creg[mt][nt] = cn;
                float hv = sigt(go) * tanhapx(cn);
                AHW[row * KHP + j] = __float2half_rn(hv);
                if (last) g_h[(blk * LNODES + row) * HH + j] = hv;
            }
        };

        // ---- m-tile triples: B fragments loaded once per 3 tiles ----
#pragma unroll
        for (int grp = 0; grp < 3; ++grp) {
            const int m0 = 3 * grp;

            float acc[3][4][4];
#pragma unroll
            for (int t = 0; t < 3; ++t)
#pragma unroll
                for (int nt = 0; nt < 4; ++nt) {
                    acc[t][nt][0] = bias0[nt]; acc[t][nt][1] = bias1[nt];
                    acc[t][nt][2] = bias0[nt]; acc[t][nt][3] = bias1[nt];
                }
            // x-part (B in registers)
#pragma unroll
            for (int ks = 0; ks < 2; ++ks) {
#pragma unroll
                for (int t = 0; t < 3; ++t) {
                    uint32_t a[4];
                    ldm_x4(axb + (uint32_t)((m0 + t) * 16 * (KXP * 2) + ks * 32), a);
#pragma unroll
                    for (int np = 0; np < 2; ++np) {
                        mma16816(acc[t][2 * np],     a[0], a[1], a[2], a[3], bxf[ks][np][0], bxf[ks][np][1]);
                        mma16816(acc[t][2 * np + 1], a[0], a[1], a[2], a[3], bxf[ks][np][2], bxf[ks][np][3]);
                    }
                }
            }
            // h-part: per ks, load B once, use for all 3 tiles
#pragma unroll
            for (int ks = 0; ks < 8; ++ks) {
                uint32_t b0[4], b1[4];
                ldm_x4(whb[0] + (((uint32_t)(ks * 32) + bko2) ^ xorv), b0);
                ldm_x4(whb[1] + (((uint32_t)(ks * 32) + bko2) ^ xorv), b1);
#pragma unroll
                for (int t = 0; t < 3; ++t) {
                    uint32_t a[4];
                    ldm_x4(ahb_r + (uint32_t)((m0 + t) * 16 * (KHP * 2) + ks * 32), a);
                    mma16816(acc[t][0], a[0], a[1], a[2], a[3], b0[0], b0[1]);
                    mma16816(acc[t][1], a[0], a[1], a[2], a[3], b0[2], b0[3]);
                    mma16816(acc[t][2], a[0], a[1], a[2], a[3], b1[0], b1[1]);
                    mma16816(acc[t][3], a[0], a[1], a[2], a[3], b1[2], b1[3]);
                }
            }

#pragma unroll
            for (int t = 0; t < 3; ++t) epilogue(m0 + t, acc[t]);
        }
        __syncthreads();
    }
}

// ---------------- CSR build ----------------------------------------------------
__global__ void csr_count_kernel(const int* __restrict__ ei) {
    int e = blockIdx.x * blockDim.x + threadIdx.x;
    if (e >= ETOT) return;
    int d = (e < EE) ? ei[EE + e] : (e - EE);
    atomicAdd(&g_cnt[d], 1);
}
__global__ __launch_bounds__(1024) void csr_scan_kernel() {
    __shared__ int swarp[32];
    const int t = threadIdx.x;
    const int lane = t & 31, wid = t >> 5;
    const int ITEMS = (NN + 1023) / 1024;
    const int base = t * ITEMS;

    int c[ITEMS];
    int total = 0;
#pragma unroll
    for (int i = 0; i < ITEMS; ++i) {
        int idx = base + i;
        c[i] = (idx < NN) ? g_cnt[idx] : 0;
        total += c[i];
        if (idx < NN) g_cnt[idx] = 0;
    }
    int incl = total;
#pragma unroll
    for (int o = 1; o < 32; o <<= 1) {
        int v = __shfl_up_sync(0xffffffffu, incl, o);
        if (lane >= o) incl += v;
    }
    if (lane == 31) swarp[wid] = incl;
    __syncthreads();
    if (wid == 0) {
        int w = swarp[lane];
        int wi = w;
#pragma unroll
        for (int o = 1; o < 32; o <<= 1) {
            int v = __shfl_up_sync(0xffffffffu, wi, o);
            if (lane >= o) wi += v;
        }
        swarp[lane] = wi - w;
    }
    __syncthreads();
    int run = swarp[wid] + (incl - total);
#pragma unroll
    for (int i = 0; i < ITEMS; ++i) {
        int idx = base + i;
        if (idx < NN) {
            g_row[idx] = run;
            g_cur[idx] = run;
            run += c[i];
        }
    }
    if (t == 1023) g_row[NN] = run;
}
__global__ void csr_scatter_kernel(const int* __restrict__ ei) {
    int e = blockIdx.x * blockDim.x + threadIdx.x;
    if (e >= ETOT) return;
    int s, d;
    if (e < EE) { s = ei[e]; d = ei[EE + e]; } else { s = e - EE; d = s; }
    int pos = atomicAdd(&g_cur[d], 1);
    g_csr[pos] = s;
}

// ---------------- fused GAT dense: xh = X@W (HMMA) + attn dots ----------------
__global__ __launch_bounds__(128) void gat_gemm_attn_kernel(
    const float* __restrict__ W, const float* __restrict__ a_src,
    const float* __restrict__ a_dst, int layer)
{
    const float* __restrict__ X = (layer == 0) ? g_h : g_feat;
    extern __shared__ char smem[];
    float* sas = (float*)(smem + GOFF_AS);
    float* sad = (float*)(smem + GOFF_AD);
    const uint32_t sA = (uint32_t)__cvta_generic_to_shared(smem + GOFF_A);
    const uint32_t sB = (uint32_t)__cvta_generic_to_shared(smem + GOFF_B);

    const int tid = threadIdx.x;
    const int n64 = blockIdx.x * 64;

    for (int i = tid; i < 64 * 128; i += 128) {
        int r = i >> 7, k = i & 127;
        float v = (n64 + r < NN) ? X[(n64 + r) * GGDIM + k] : 0.0f;
        uint32_t byte = (uint32_t)(r * 256 + (((k >> 3) ^ (r & 7)) << 4) + ((k & 7) << 1));
        *(__half*)(smem + GOFF_A + byte) = __float2half_rn(v);
    }
    for (int i = tid; i < 128 * 128; i += 128) {
        int n = i >> 7, k = i & 127;
        uint32_t byte = (uint32_t)(n * 256 + (((k >> 3) ^ (n & 7)) << 4) + ((k & 7) << 1));
        *(__half*)(smem + GOFF_B + byte) = __float2half_rn(W[k * GGDIM + n]);
    }
    if (tid < 128) { sas[tid] = a_src[tid]; sad[tid] = a_dst[tid]; }
    __syncthreads();

    const int wid  = tid >> 5;
    const int lane = tid & 31;
    const int g    = lane >> 2;
    const int cc   = lane & 3;
    const int sub = lane >> 3, rr = lane & 7;
    const int arow = (sub & 1) * 8 + rr;
    const int akof = (sub >> 1) * 8;
    const int bcol = rr + ((sub >> 1) * 8);
    const int bkof = (sub & 1) * 8;
    const uint32_t xorv = (uint32_t)(rr << 4);
    const uint32_t ako2 = (uint32_t)(akof << 1);
    const uint32_t bko2 = (uint32_t)(bkof << 1);
    const uint32_t arowb = sA + (uint32_t)(wid * 16 + arow) * 256;

    float acc[16][4];
#pragma unroll
    for (int q = 0; q < 16; ++q)
#pragma unroll
        for (int z = 0; z < 4; ++z) acc[q][z] = 0.0f;

#pragma unroll
    for (int ks = 0; ks < 8; ++ks) {
        uint32_t a[4];
        ldm_x4(arowb + (((uint32_t)(ks * 32) + ako2) ^ xorv), a);
#pragma unroll
        for (int np = 0; np < 8; ++np) {
            uint32_t b[4];
            ldm_x4(sB + (uint32_t)(np * 16 + bcol) * 256 + (((uint32_t)(ks * 32) + bko2) ^ xorv), b);
            mma16816(acc[2 * np],     a[0], a[1], a[2], a[3], b[0], b[1]);
            mma16816(acc[2 * np + 1], a[0], a[1], a[2], a[3], b[2], b[3]);
        }
    }

    const int gr0 = n64 + wid * 16 + g;
    const int gr1 = gr0 + 8;
#pragma unroll
    for (int np = 0; np < 8; ++np) {
        int c0 = np * 16 + 2 * cc, c1 = np * 16 + 8 + 2 * cc;
        if (gr0 < NN) {
            *(float2*)&g_xh[gr0 * GGDIM + c0] = make_float2(acc[2 * np][0], acc[2 * np][1]);
            *(float2*)&g_xh[gr0 * GGDIM + c1] = make_float2(acc[2 * np + 1][0], acc[2 * np + 1][1]);
        }
        if (gr1 < NN) {
            *(float2*)&g_xh[gr1 * GGDIM + c0] = make_float2(acc[2 * np][2], acc[2 * np][3]);
            *(float2*)&g_xh[gr1 * GGDIM + c1] = make_float2(acc[2 * np + 1][2], acc[2 * np + 1][3]);
        }
    }

    float rs0[4], rs1[4], rd0[4], rd1[4];
#pragma unroll
    for (int h = 0; h < 4; ++h) {
        float s0 = 0.0f, s1 = 0.0f, d0 = 0.0f, d1 = 0.0f;
#pragma unroll
        for (int tti = 0; tti < 4; ++tti) {
            int np = h * 2 + (tti >> 1);
            int ai = 2 * np + (tti & 1);
            int col = np * 16 + (tti & 1) * 8 + 2 * cc;
            float w0s = sas[col], w1s = sas[col + 1];
            float w0d = sad[col], w1d = sad[col + 1];
            s0 += acc[ai][0] * w0s + acc[ai][1] * w1s;
            s1 += acc[ai][2] * w0s + acc[ai][3] * w1s;
            d0 += acc[ai][0] * w0d + acc[ai][1] * w1d;
            d1 += acc[ai][2] * w0d + acc[ai][3] * w1d;
        }
        s0 += __shfl_xor_sync(0xffffffffu, s0, 1); s0 += __shfl_xor_sync(0xffffffffu, s0, 2);
        s1 += __shfl_xor_sync(0xffffffffu, s1, 1); s1 += __shfl_xor_sync(0xffffffffu, s1, 2);
        d0 += __shfl_xor_sync(0xffffffffu, d0, 1); d0 += __shfl_xor_sync(0xffffffffu, d0, 2);
        d1 += __shfl_xor_sync(0xffffffffu, d1, 1); d1 += __shfl_xor_sync(0xffffffffu, d1, 2);
        rs0[h] = s0; rs1[h] = s1; rd0[h] = d0; rd1[h] = d1;
    }
    if (gr0 < NN) { g_asr[gr0 * 4 + cc] = rs0[cc]; g_adt[gr0 * 4 + cc] = rd0[cc]; }
    if (gr1 < NN) { g_asr[gr1 * 4 + cc] = rs1[cc]; g_adt[gr1 * 4 + cc] = rd1[cc]; }
}

// -------- fused softmax + aggregate + bias + ELU (+ optional head) ------------
__global__ __launch_bounds__(256) void gat_agg_kernel(
    const float* __restrict__ bias, const float* __restrict__ Wh,
    const float* __restrict__ bh, float* __restrict__ out, int last)
{
    const int d    = (blockIdx.x * 256 + threadIdx.x) >> 5;
    const int lane = threadIdx.x & 31;
    if (d >= NN) return;
    const int start = g_row[d], end = g_row[d + 1];

    const float4 adt4 = *(const float4*)&g_adt[d * 4];

    float s0 = 0.0f, s1 = 0.0f, s2 = 0.0f, s3 = 0.0f;
    for (int idx = start + lane; idx < end; idx += 32) {
        int s = g_csr[idx];
        float4 a = *(const float4*)&g_asr[s * 4];
        s0 += __expf(lrelu(a.x + adt4.x));
        s1 += __expf(lrelu(a.y + adt4.y));
        s2 += __expf(lrelu(a.z + adt4.z));
        s3 += __expf(lrelu(a.w + adt4.w));
    }
#pragma unroll
    for (int off = 16; off > 0; off >>= 1) {
        s0 += __shfl_xor_sync(0xffffffffu, s0, off);
        s1 += __shfl_xor_sync(0xffffffffu, s1, off);
        s2 += __shfl_xor_sync(0xffffffffu, s2, off);
        s3 += __shfl_xor_sync(0xffffffffu, s3, off);
    }

    const int head = lane >> 3;
    float adt_h, den_h;
    if (head == 0)      { adt_h = adt4.x; den_h = s0; }
    else if (head == 1) { adt_h = adt4.y; den_h = s1; }
    else if (head == 2) { adt_h = adt4.z; den_h = s2; }
    else                { adt_h = adt4.w; den_h = s3; }
    const float inv_den = 1.0f / (den_h + 1e-16f);

    float4 acc = make_float4(0.0f, 0.0f, 0.0f, 0.0f);
    for (int idx = start; idx < end; ++idx) {
        int s = g_csr[idx];
        float as_h = g_asr[s * 4 + head];
        float alpha = __expf(lrelu(as_h + adt_h)) * inv_den;
        float4 xv = *(const float4*)&g_xh[s * GGDIM + lane * 4];
        acc.x = fmaf(alpha, xv.x, acc.x);
        acc.y = fmaf(alpha, xv.y, acc.y);
        acc.z = fmaf(alpha, xv.z, acc.z);
        acc.w = fmaf(alpha, xv.w, acc.w);
    }

    const float4 bv = *(const float4*)&bias[lane * 4];
    float4 outv;
    float v;
    v = acc.x + bv.x; outv.x = v > 0.0f ? v : (__expf(v) - 1.0f);
    v = acc.y + bv.y; outv.y = v > 0.0f ? v : (__expf(v) - 1.0f);
    v = acc.z + bv.z; outv.z = v > 0.0f ? v : (__expf(v) - 1.0f);
    v = acc.w + bv.w; outv.w = v > 0.0f ? v : (__expf(v) - 1.0f);

    if (!last) {
        *(float4*)&g_feat[d * GGDIM + lane * 4] = outv;
    } else {
        int ch = lane * 4;
        float p0 = outv.x * Wh[2 * ch + 0] + outv.y * Wh[2 * ch + 2]
                 + outv.z * Wh[2 * ch + 4] + outv.w * Wh[2 * ch + 6];
        float p1 = outv.x * Wh[2 * ch + 1] + outv.y * Wh[2 * ch + 3]
                 + outv.z * Wh[2 * ch + 5] + outv.w * Wh[2 * ch + 7];
#pragma unroll
        for (int off = 16; off > 0; off >>= 1) {
            p0 += __shfl_xor_sync(0xffffffffu, p0, off);
            p1 += __shfl_xor_sync(0xffffffffu, p1, off);
        }
        if (lane == 0) {
            out[2 * d + 0] = p0 + bh[0];
            out[2 * d + 1] = p1 + bh[1];
        }
    }
}

// ---------------- launch --------------------------------------------------------
extern "C" void kernel_launch(void* const* d_in, const int* in_sizes, int n_in,
                              void* d_out, int out_size) {
    const float* x_win  = (const float*)d_in[0];
    const int*   ei     = (const int*)  d_in[1];
    const float* Wih    = (const float*)d_in[2];
    const float* Whh    = (const float*)d_in[3];
    const float* bih    = (const float*)d_in[4];
    const float* bhh    = (const float*)d_in[5];
    const float* W1     = (const float*)d_in[6];
    const float* asrc1  = (const float*)d_in[7];
    const float* adst1  = (const float*)d_in[8];
    const float* b1     = (const float*)d_in[9];
    const float* W2     = (const float*)d_in[10];
    const float* asrc2  = (const float*)d_in[11];
    const float* adst2  = (const float*)d_in[12];
    const float* b2     = (const float*)d_in[13];
    const float* Wh     = (const float*)d_in[14];
    const float* bh     = (const float*)d_in[15];
    float* out = (float*)d_out;

    cudaFuncSetAttribute(lstm_all_kernel,
                         cudaFuncAttributeMaxDynamicSharedMemorySize, SMEM_TOTAL);
    cudaFuncSetAttribute(gat_gemm_attn_kernel,
                         cudaFuncAttributeMaxDynamicSharedMemorySize, GSMEM);

    lstm_all_kernel<<<LGRID, LTHR, SMEM_TOTAL>>>(x_win, Wih, Whh, bih, bhh);

    csr_count_kernel<<<(ETOT + 255) / 256, 256>>>(ei);
    csr_scan_kernel<<<1, 1024>>>();
    csr_scatter_kernel<<<(ETOT + 255) / 256, 256>>>(ei);

    for (int layer = 0; layer < 2; layer++) {
        const float* W    = layer ? W2    : W1;
        const float* asrc = layer ? asrc2 : asrc1;
        const float* adst = layer ? adst2 : adst1;
        const float* bb   = layer ? b2    : b1;

        gat_gemm_attn_kernel<<<(NN + 63) / 64, 128, GSMEM>>>(W, asrc, adst, layer);
        gat_agg_kernel<<<(NN * 32 + 255) / 256, 256>>>(bb, Wh, bh, out, layer);
    }
}

// round 13
// speedup vs baseline: 1.0778x; 1.0637x over previous
#include <cuda_runtime.h>
#include <cuda_fp16.h>
#include <math.h>
#include <stdint.h>

// ---------------- problem constants ------------------------------------------
#define NN      20000
#define TT      60
#define DDIM    20
#define HH      128
#define GGDIM   128
#define NHEADS  4
#define CCH     32
#define EE      320000
#define ETOT    (EE + NN)
#define G4      512
#define LNODES  144
#define MTILES  9
#define LGRID   139
#define GSTR    (LGRID * LNODES)
#define LTHR    512

#define KXP     40
#define KHP     136
#define AXE     (LNODES * DDIM)

// ---------------- LSTM smem layout (bytes) -----------------------------------
#define OFF_AH1  0
#define OFF_WX   0
#define OFF_WH   40960
#define OFF_AX   172032
#define OFF_AH0  183552
#define OFF_BIAS 222720
#define SMEM_TOTAL 224768

// ---------------- GAT gemm+attn smem layout (bytes, dynamic) ------------------
#define GOFF_A   0
#define GOFF_B   16384
#define GOFF_AS  49152
#define GOFF_AD  49664
#define GSMEM    50176

// ---------------- scratch (device globals) ------------------------------------
__device__ float g_h[GSTR * HH];
__device__ float g_xh[NN * GGDIM];
__device__ float g_feat[NN * GGDIM];
__device__ float g_asr[NN * NHEADS];
__device__ float g_adt[NN * NHEADS];
__device__ int   g_cnt[NN];          // loader-zeroed; re-zeroed by scan each call
__device__ int   g_row[NN + 1];
__device__ int   g_cur[NN];
__device__ int   g_csr[ETOT];

// ---------------- helpers -----------------------------------------------------
__device__ __forceinline__ float tanhapx(float x) {
    float y; asm("tanh.approx.f32 %0, %1;" : "=f"(y) : "f"(x)); return y;
}
__device__ __forceinline__ float sigt(float x) {
    return fmaf(tanhapx(0.5f * x), 0.5f, 0.5f);
}
__device__ __forceinline__ void mma16816(float* d,
                                         uint32_t a0, uint32_t a1, uint32_t a2, uint32_t a3,
                                         uint32_t b0, uint32_t b1) {
    asm volatile(
        "mma.sync.aligned.m16n8k16.row.col.f32.f16.f16.f32 "
        "{%0,%1,%2,%3}, {%4,%5,%6,%7}, {%8,%9}, {%0,%1,%2,%3};"
        : "+f"(d[0]), "+f"(d[1]), "+f"(d[2]), "+f"(d[3])
        : "r"(a0), "r"(a1), "r"(a2), "r"(a3), "r"(b0), "r"(b1));
}
__device__ __forceinline__ void ldm_x4(uint32_t addr, uint32_t* r) {
    asm volatile("ldmatrix.sync.aligned.m8n8.x4.shared.b16 {%0,%1,%2,%3}, [%4];"
                 : "=r"(r[0]), "=r"(r[1]), "=r"(r[2]), "=r"(r[3]) : "r"(addr));
}
__device__ __forceinline__ float lrelu(float v) { return v > 0.0f ? v : 0.2f * v; }

// ---------------- persistent LSTM kernel (paired m-tiles, dbl-buffered AH) ----
__global__ __launch_bounds__(LTHR, 1) void lstm_all_kernel(
    const float* __restrict__ x,
    const float* __restrict__ Wih, const float* __restrict__ Whh,
    const float* __restrict__ bih, const float* __restrict__ bhh)
{
    extern __shared__ char smem[];
    __half* WX = (__half*)(smem + OFF_WX);
    __half* AX = (__half*)(smem + OFF_AX);
    float*  sbias = (float*)(smem + OFF_BIAS);
    const uint32_t sWX  = (uint32_t)__cvta_generic_to_shared(smem + OFF_WX);
    const uint32_t sWH  = (uint32_t)__cvta_generic_to_shared(smem + OFF_WH);
    const uint32_t sAX  = (uint32_t)__cvta_generic_to_shared(smem + OFF_AX);
    const uint32_t sAH0 = (uint32_t)__cvta_generic_to_shared(smem + OFF_AH0);
    const uint32_t sAH1 = (uint32_t)__cvta_generic_to_shared(smem + OFF_AH1);

    const int tid = threadIdx.x;
    const int blk = blockIdx.x;

    for (int i = tid; i < OFF_BIAS / 4; i += LTHR) ((uint32_t*)smem)[i] = 0;
    __syncthreads();

    for (int i = tid; i < G4 * DDIM; i += LTHR) {
        int n = i / DDIM, k = i - n * DDIM;
        int row = (n & 3) * HH + (n >> 2);
        WX[n * KXP + k] = __float2half_rn(Wih[row * DDIM + k]);
    }
    for (int i = tid; i < G4 * HH; i += LTHR) {
        int n = i >> 7, k = i & 127;
        int row = (n & 3) * HH + (n >> 2);
        uint32_t byte = (uint32_t)(n * 256 + ((((k >> 3) ^ (n & 7)) << 4)) + ((k & 7) << 1));
        *(__half*)(smem + OFF_WH + byte) = __float2half_rn(Whh[row * HH + k]);
    }
    for (int i = tid; i < G4; i += LTHR) {
        int row = (i & 3) * HH + (i >> 2);
        sbias[i] = bih[row] + bhh[row];
    }
    __syncthreads();

    const int wid  = tid >> 5;
    const int lane = tid & 31;
    const int g    = lane >> 2;
    const int cc   = lane & 3;
    const int n0   = wid * 32;
    const bool odd = (lane & 1);
    const int jbase = (n0 >> 2) + (cc >> 1);

    const int sub = lane >> 3, rr = lane & 7;
    const int arow = (sub & 1) * 8 + rr;
    const int akof = (sub >> 1) * 8;
    const int bcol = rr + ((sub >> 1) * 8);
    const int bkof = (sub & 1) * 8;
    const uint32_t laneAH = (uint32_t)(arow * KHP + akof) * 2;
    const uint32_t axb  = sAX  + (uint32_t)(arow * KXP + akof) * 2;
    const uint32_t ahb0 = sAH0 + laneAH;
    const uint32_t ahb1 = sAH1 + laneAH;
    const uint32_t xorv = (uint32_t)(rr << 4);
    uint32_t wxb[2], whb[2];
#pragma unroll
    for (int np = 0; np < 2; ++np) {
        wxb[np] = sWX + (uint32_t)((n0 + np * 16 + bcol) * KXP + bkof) * 2;
        whb[np] = sWH + (uint32_t)(n0 + np * 16 + bcol) * 256;
    }
    const uint32_t bko2 = (uint32_t)(bkof << 1);

    float bias0[4], bias1[4];
#pragma unroll
    for (int nt = 0; nt < 4; ++nt) {
        bias0[nt] = sbias[n0 + nt * 8 + 2 * cc];
        bias1[nt] = sbias[n0 + nt * 8 + 2 * cc + 1];
    }

    uint32_t bxf[2][2][4];
#pragma unroll
    for (int ks = 0; ks < 2; ++ks)
#pragma unroll
        for (int np = 0; np < 2; ++np)
            ldm_x4(wxb[np] + (uint32_t)(ks * 32), bxf[ks][np]);

    float creg[MTILES][4];
#pragma unroll
    for (int mt = 0; mt < MTILES; ++mt)
#pragma unroll
        for (int nt = 0; nt < 4; ++nt) creg[mt][nt] = 0.0f;

    __syncthreads();

    for (int s = 0; s < TT; ++s) {
        for (int i = tid; i < AXE; i += LTHR) {
            int mm = i / DDIM, k = i - mm * DDIM;
            int n = blk * LNODES + mm;
            AX[mm * KXP + k] = __float2half_rn(n < NN ? x[n * (TT * DDIM) + s * DDIM + k] : 0.0f);
        }
        __syncthreads();

        const bool last = (s == TT - 1);
        const uint32_t ahb_r = (s & 1) ? ahb1 : ahb0;
        __half* AHW = (__half*)(smem + ((s & 1) ? OFF_AH0 : OFF_AH1));

        auto epilogue = [&](int mt, float (&acc)[4][4]) {
#pragma unroll
            for (int nt = 0; nt < 4; ++nt) {
                float c0 = acc[nt][0], c1 = acc[nt][1], c2 = acc[nt][2], c3 = acc[nt][3];
                float x0 = __shfl_xor_sync(0xffffffffu, c0, 1);
                float x1 = __shfl_xor_sync(0xffffffffu, c1, 1);
                float x2 = __shfl_xor_sync(0xffffffffu, c2, 1);
                float x3 = __shfl_xor_sync(0xffffffffu, c3, 1);
                float gi, gf, gg, go; int row;
                if (!odd) { gi = c0; gf = c1; gg = x0; go = x1; row = mt * 16 + g; }
                else      { gi = x2; gf = x3; gg = c2; go = c3; row = mt * 16 + g + 8; }
                int j = jbase + nt * 2;
                float cold = creg[mt][nt];
                float cn = sigt(gf) * cold + sigt(gi) * tanhapx(gg);
                creg[mt][nt] = cn;
                float hv = sigt(go) * tanhapx(cn);
                AHW[row * KHP + j] = __float2half_rn(hv);
                if (last) g_h[(blk * LNODES + row) * HH + j] = hv;
            }
        };

#pragma unroll
        for (int p = 0; p < 5; ++p) {
            const int m0 = 2 * p;
            const bool has1 = (m0 + 1 < MTILES);

            float acc0[4][4], acc1[4][4];
#pragma unroll
            for (int nt = 0; nt < 4; ++nt) {
                acc0[nt][0] = bias0[nt]; acc0[nt][1] = bias1[nt];
                acc0[nt][2] = bias0[nt]; acc0[nt][3] = bias1[nt];
                acc1[nt][0] = bias0[nt]; acc1[nt][1] = bias1[nt];
                acc1[nt][2] = bias0[nt]; acc1[nt][3] = bias1[nt];
            }
#pragma unroll
            for (int ks = 0; ks < 2; ++ks) {
                uint32_t a[4];
                ldm_x4(axb + (uint32_t)(m0 * 16 * (KXP * 2) + ks * 32), a);
#pragma unroll
                for (int np = 0; np < 2; ++np) {
                    mma16816(acc0[2 * np],     a[0], a[1], a[2], a[3], bxf[ks][np][0], bxf[ks][np][1]);
                    mma16816(acc0[2 * np + 1], a[0], a[1], a[2], a[3], bxf[ks][np][2], bxf[ks][np][3]);
                }
                if (has1) {
                    uint32_t a1[4];
                    ldm_x4(axb + (uint32_t)((m0 + 1) * 16 * (KXP * 2) + ks * 32), a1);
#pragma unroll
                    for (int np = 0; np < 2; ++np) {
                        mma16816(acc1[2 * np],     a1[0], a1[1], a1[2], a1[3], bxf[ks][np][0], bxf[ks][np][1]);
                        mma16816(acc1[2 * np + 1], a1[0], a1[1], a1[2], a1[3], bxf[ks][np][2], bxf[ks][np][3]);
                    }
                }
            }
#pragma unroll
            for (int ks = 0; ks < 8; ++ks) {
                uint32_t b0[4], b1[4];
                ldm_x4(whb[0] + (((uint32_t)(ks * 32) + bko2) ^ xorv), b0);
                ldm_x4(whb[1] + (((uint32_t)(ks * 32) + bko2) ^ xorv), b1);
                uint32_t a[4];
                ldm_x4(ahb_r + (uint32_t)(m0 * 16 * (KHP * 2) + ks * 32), a);
                mma16816(acc0[0], a[0], a[1], a[2], a[3], b0[0], b0[1]);
                mma16816(acc0[1], a[0], a[1], a[2], a[3], b0[2], b0[3]);
                mma16816(acc0[2], a[0], a[1], a[2], a[3], b1[0], b1[1]);
                mma16816(acc0[3], a[0], a[1], a[2], a[3], b1[2], b1[3]);
                if (has1) {
                    uint32_t a1[4];
                    ldm_x4(ahb_r + (uint32_t)((m0 + 1) * 16 * (KHP * 2) + ks * 32), a1);
                    mma16816(acc1[0], a1[0], a1[1], a1[2], a1[3], b0[0], b0[1]);
                    mma16816(acc1[1], a1[0], a1[1], a1[2], a1[3], b0[2], b0[3]);
                    mma16816(acc1[2], a1[0], a1[1], a1[2], a1[3], b1[0], b1[1]);
                    mma16816(acc1[3], a1[0], a1[1], a1[2], a1[3], b1[2], b1[3]);
                }
            }

            epilogue(m0, acc0);
            if (has1) epilogue(m0 + 1, acc1);
        }
        __syncthreads();
    }
}

// ---------------- CSR build ----------------------------------------------------
__global__ void csr_count_kernel(const int* __restrict__ ei) {
    int e = blockIdx.x * blockDim.x + threadIdx.x;
    if (e >= ETOT) return;
    int d = (e < EE) ? ei[EE + e] : (e - EE);
    atomicAdd(&g_cnt[d], 1);
}
__global__ __launch_bounds__(1024) void csr_scan_kernel() {
    __shared__ int swarp[32];
    const int t = threadIdx.x;
    const int lane = t & 31, wid = t >> 5;
    const int ITEMS = (NN + 1023) / 1024;
    const int base = t * ITEMS;

    int c[ITEMS];
    int total = 0;
#pragma unroll
    for (int i = 0; i < ITEMS; ++i) {
        int idx = base + i;
        c[i] = (idx < NN) ? g_cnt[idx] : 0;
        total += c[i];
        if (idx < NN) g_cnt[idx] = 0;
    }
    int incl = total;
#pragma unroll
    for (int o = 1; o < 32; o <<= 1) {
        int v = __shfl_up_sync(0xffffffffu, incl, o);
        if (lane >= o) incl += v;
    }
    if (lane == 31) swarp[wid] = incl;
    __syncthreads();
    if (wid == 0) {
        int w = swarp[lane];
        int wi = w;
#pragma unroll
        for (int o = 1; o < 32; o <<= 1) {
            int v = __shfl_up_sync(0xffffffffu, wi, o);
            if (lane >= o) wi += v;
        }
        swarp[lane] = wi - w;
    }
    __syncthreads();
    int run = swarp[wid] + (incl - total);
#pragma unroll
    for (int i = 0; i < ITEMS; ++i) {
        int idx = base + i;
        if (idx < NN) {
            g_row[idx] = run;
            g_cur[idx] = run;
            run += c[i];
        }
    }
    if (t == 1023) g_row[NN] = run;
}
__global__ void csr_scatter_kernel(const int* __restrict__ ei) {
    int e = blockIdx.x * blockDim.x + threadIdx.x;
    if (e >= ETOT) return;
    int s, d;
    if (e < EE) { s = ei[e]; d = ei[EE + e]; } else { s = e - EE; d = s; }
    int pos = atomicAdd(&g_cur[d], 1);
    g_csr[pos] = s;
}

// ---------------- fused GAT dense: xh = X@W (HMMA) + attn dots ----------------
__global__ __launch_bounds__(128) void gat_gemm_attn_kernel(
    const float* __restrict__ W, const float* __restrict__ a_src,
    const float* __restrict__ a_dst, int layer)
{
    const float* __restrict__ X = (layer == 0) ? g_h : g_feat;
    extern __shared__ char smem[];
    float* sas = (float*)(smem + GOFF_AS);
    float* sad = (float*)(smem + GOFF_AD);
    const uint32_t sA = (uint32_t)__cvta_generic_to_shared(smem + GOFF_A);
    const uint32_t sB = (uint32_t)__cvta_generic_to_shared(smem + GOFF_B);

    const int tid = threadIdx.x;
    const int n64 = blockIdx.x * 64;

    for (int i = tid; i < 64 * 128; i += 128) {
        int r = i >> 7, k = i & 127;
        float v = (n64 + r < NN) ? X[(n64 + r) * GGDIM + k] : 0.0f;
        uint32_t byte = (uint32_t)(r * 256 + (((k >> 3) ^ (r & 7)) << 4) + ((k & 7) << 1));
        *(__half*)(smem + GOFF_A + byte) = __float2half_rn(v);
    }
    for (int i = tid; i < 128 * 128; i += 128) {
        int n = i >> 7, k = i & 127;
        uint32_t byte = (uint32_t)(n * 256 + (((k >> 3) ^ (n & 7)) << 4) + ((k & 7) << 1));
        *(__half*)(smem + GOFF_B + byte) = __float2half_rn(W[k * GGDIM + n]);
    }
    if (tid < 128) { sas[tid] = a_src[tid]; sad[tid] = a_dst[tid]; }
    __syncthreads();

    const int wid  = tid >> 5;
    const int lane = tid & 31;
    const int g    = lane >> 2;
    const int cc   = lane & 3;
    const int sub = lane >> 3, rr = lane & 7;
    const int arow = (sub & 1) * 8 + rr;
    const int akof = (sub >> 1) * 8;
    const int bcol = rr + ((sub >> 1) * 8);
    const int bkof = (sub & 1) * 8;
    const uint32_t xorv = (uint32_t)(rr << 4);
    const uint32_t ako2 = (uint32_t)(akof << 1);
    const uint32_t bko2 = (uint32_t)(bkof << 1);
    const uint32_t arowb = sA + (uint32_t)(wid * 16 + arow) * 256;

    float acc[16][4];
#pragma unroll
    for (int q = 0; q < 16; ++q)
#pragma unroll
        for (int z = 0; z < 4; ++z) acc[q][z] = 0.0f;

#pragma unroll
    for (int ks = 0; ks < 8; ++ks) {
        uint32_t a[4];
        ldm_x4(arowb + (((uint32_t)(ks * 32) + ako2) ^ xorv), a);
#pragma unroll
        for (int np = 0; np < 8; ++np) {
            uint32_t b[4];
            ldm_x4(sB + (uint32_t)(np * 16 + bcol) * 256 + (((uint32_t)(ks * 32) + bko2) ^ xorv), b);
            mma16816(acc[2 * np],     a[0], a[1], a[2], a[3], b[0], b[1]);
            mma16816(acc[2 * np + 1], a[0], a[1], a[2], a[3], b[2], b[3]);
        }
    }

    const int gr0 = n64 + wid * 16 + g;
    const int gr1 = gr0 + 8;
#pragma unroll
    for (int np = 0; np < 8; ++np) {
        int c0 = np * 16 + 2 * cc, c1 = np * 16 + 8 + 2 * cc;
        if (gr0 < NN) {
            *(float2*)&g_xh[gr0 * GGDIM + c0] = make_float2(acc[2 * np][0], acc[2 * np][1]);
            *(float2*)&g_xh[gr0 * GGDIM + c1] = make_float2(acc[2 * np + 1][0], acc[2 * np + 1][1]);
        }
        if (gr1 < NN) {
            *(float2*)&g_xh[gr1 * GGDIM + c0] = make_float2(acc[2 * np][2], acc[2 * np][3]);
            *(float2*)&g_xh[gr1 * GGDIM + c1] = make_float2(acc[2 * np + 1][2], acc[2 * np + 1][3]);
        }
    }

    float rs0[4], rs1[4], rd0[4], rd1[4];
#pragma unroll
    for (int h = 0; h < 4; ++h) {
        float s0 = 0.0f, s1 = 0.0f, d0 = 0.0f, d1 = 0.0f;
#pragma unroll
        for (int tti = 0; tti < 4; ++tti) {
            int np = h * 2 + (tti >> 1);
            int ai = 2 * np + (tti & 1);
            int col = np * 16 + (tti & 1) * 8 + 2 * cc;
            float w0s = sas[col], w1s = sas[col + 1];
            float w0d = sad[col], w1d = sad[col + 1];
            s0 += acc[ai][0] * w0s + acc[ai][1] * w1s;
            s1 += acc[ai][2] * w0s + acc[ai][3] * w1s;
            d0 += acc[ai][0] * w0d + acc[ai][1] * w1d;
            d1 += acc[ai][2] * w0d + acc[ai][3] * w1d;
        }
        s0 += __shfl_xor_sync(0xffffffffu, s0, 1); s0 += __shfl_xor_sync(0xffffffffu, s0, 2);
        s1 += __shfl_xor_sync(0xffffffffu, s1, 1); s1 += __shfl_xor_sync(0xffffffffu, s1, 2);
        d0 += __shfl_xor_sync(0xffffffffu, d0, 1); d0 += __shfl_xor_sync(0xffffffffu, d0, 2);
        d1 += __shfl_xor_sync(0xffffffffu, d1, 1); d1 += __shfl_xor_sync(0xffffffffu, d1, 2);
        rs0[h] = s0; rs1[h] = s1; rd0[h] = d0; rd1[h] = d1;
    }
    if (gr0 < NN) { g_asr[gr0 * 4 + cc] = rs0[cc]; g_adt[gr0 * 4 + cc] = rd0[cc]; }
    if (gr1 < NN) { g_asr[gr1 * 4 + cc] = rs1[cc]; g_adt[gr1 * 4 + cc] = rd1[cc]; }
}

// -------- fused softmax + aggregate + bias + ELU (+ optional head) ------------
__global__ __launch_bounds__(256) void gat_agg_kernel(
    const float* __restrict__ bias, const float* __restrict__ Wh,
    const float* __restrict__ bh, float* __restrict__ out, int last)
{
    const int d    = (blockIdx.x * 256 + threadIdx.x) >> 5;
    const int lane = threadIdx.x & 31;
    if (d >= NN) return;
    const int start = g_row[d], end = g_row[d + 1];

    const float4 adt4 = *(const float4*)&g_adt[d * 4];

    float s0 = 0.0f, s1 = 0.0f, s2 = 0.0f, s3 = 0.0f;
    for (int idx = start + lane; idx < end; idx += 32) {
        int s = g_csr[idx];
        float4 a = *(const float4*)&g_asr[s * 4];
        s0 += __expf(lrelu(a.x + adt4.x));
        s1 += __expf(lrelu(a.y + adt4.y));
        s2 += __expf(lrelu(a.z + adt4.z));
        s3 += __expf(lrelu(a.w + adt4.w));
    }
#pragma unroll
    for (int off = 16; off > 0; off >>= 1) {
        s0 += __shfl_xor_sync(0xffffffffu, s0, off);
        s1 += __shfl_xor_sync(0xffffffffu, s1, off);
        s2 += __shfl_xor_sync(0xffffffffu, s2, off);
        s3 += __shfl_xor_sync(0xffffffffu, s3, off);
    }

    const int head = lane >> 3;
    float adt_h, den_h;
    if (head == 0)      { adt_h = adt4.x; den_h = s0; }
    else if (head == 1) { adt_h = adt4.y; den_h = s1; }
    else if (head == 2) { adt_h = adt4.z; den_h = s2; }
    else                { adt_h = adt4.w; den_h = s3; }
    const float inv_den = 1.0f / (den_h + 1e-16f);

    float4 acc = make_float4(0.0f, 0.0f, 0.0f, 0.0f);
    for (int idx = start; idx < end; ++idx) {
        int s = g_csr[idx];
        float as_h = g_asr[s * 4 + head];
        float alpha = __expf(lrelu(as_h + adt_h)) * inv_den;
        float4 xv = *(const float4*)&g_xh[s * GGDIM + lane * 4];
        acc.x = fmaf(alpha, xv.x, acc.x);
        acc.y = fmaf(alpha, xv.y, acc.y);
        acc.z = fmaf(alpha, xv.z, acc.z);
        acc.w = fmaf(alpha, xv.w, acc.w);
    }

    const float4 bv = *(const float4*)&bias[lane * 4];
    float4 outv;
    float v;
    v = acc.x + bv.x; outv.x = v > 0.0f ? v : (__expf(v) - 1.0f);
    v = acc.y + bv.y; outv.y = v > 0.0f ? v : (__expf(v) - 1.0f);
    v = acc.z + bv.z; outv.z = v > 0.0f ? v : (__expf(v) - 1.0f);
    v = acc.w + bv.w; outv.w = v > 0.0f ? v : (__expf(v) - 1.0f);

    if (!last) {
        *(float4*)&g_feat[d * GGDIM + lane * 4] = outv;
    } else {
        int ch = lane * 4;
        float p0 = outv.x * Wh[2 * ch + 0] + outv.y * Wh[2 * ch + 2]
                 + outv.z * Wh[2 * ch + 4] + outv.w * Wh[2 * ch + 6];
        float p1 = outv.x * Wh[2 * ch + 1] + outv.y * Wh[2 * ch + 3]
                 + outv.z * Wh[2 * ch + 5] + outv.w * Wh[2 * ch + 7];
#pragma unroll
        for (int off = 16; off > 0; off >>= 1) {
            p0 += __shfl_xor_sync(0xffffffffu, p0, off);
            p1 += __shfl_xor_sync(0xffffffffu, p1, off);
        }
        if (lane == 0) {
            out[2 * d + 0] = p0 + bh[0];
            out[2 * d + 1] = p1 + bh[1];
        }
    }
}

// ---------------- launch --------------------------------------------------------
extern "C" void kernel_launch(void* const* d_in, const int* in_sizes, int n_in,
                              void* d_out, int out_size) {
    const float* x_win  = (const float*)d_in[0];
    const int*   ei     = (const int*)  d_in[1];
    const float* Wih    = (const float*)d_in[2];
    const float* Whh    = (const float*)d_in[3];
    const float* bih    = (const float*)d_in[4];
    const float* bhh    = (const float*)d_in[5];
    const float* W1     = (const float*)d_in[6];
    const float* asrc1  = (const float*)d_in[7];
    const float* adst1  = (const float*)d_in[8];
    const float* b1     = (const float*)d_in[9];
    const float* W2     = (const float*)d_in[10];
    const float* asrc2  = (const float*)d_in[11];
    const float* adst2  = (const float*)d_in[12];
    const float* b2     = (const float*)d_in[13];
    const float* Wh     = (const float*)d_in[14];
    const float* bh     = (const float*)d_in[15];
    float* out = (float*)d_out;

    // one-time host-side resources (created outside any capture; identical
    // device work is enqueued on every call)
    static cudaStream_t s_aux = nullptr;
    static cudaEvent_t  ev_fork = nullptr, ev_join = nullptr;
    static bool attr_done = false;
    if (!attr_done) {
        cudaFuncSetAttribute(lstm_all_kernel,
                             cudaFuncAttributeMaxDynamicSharedMemorySize, SMEM_TOTAL);
        cudaFuncSetAttribute(gat_gemm_attn_kernel,
                             cudaFuncAttributeMaxDynamicSharedMemorySize, GSMEM);
        cudaStreamCreateWithFlags(&s_aux, cudaStreamNonBlocking);
        cudaEventCreateWithFlags(&ev_fork, cudaEventDisableTiming);
        cudaEventCreateWithFlags(&ev_join, cudaEventDisableTiming);
        attr_done = true;
    }

    // fork: CSR build runs concurrently with the LSTM (independent inputs)
    cudaEventRecord(ev_fork, 0);
    cudaStreamWaitEvent(s_aux, ev_fork, 0);

    lstm_all_kernel<<<LGRID, LTHR, SMEM_TOTAL>>>(x_win, Wih, Whh, bih, bhh);

    csr_count_kernel<<<(ETOT + 255) / 256, 256, 0, s_aux>>>(ei);
    csr_scan_kernel<<<1, 1024, 0, s_aux>>>();
    csr_scatter_kernel<<<(ETOT + 255) / 256, 256, 0, s_aux>>>(ei);
    cudaEventRecord(ev_join, s_aux);
    cudaStreamWaitEvent(0, ev_join, 0);

    for (int layer = 0; layer < 2; layer++) {
        const float* W    = layer ? W2    : W1;
        const float* asrc = layer ? asrc2 : asrc1;
        const float* adst = layer ? adst2 : adst1;
        const float* bb   = layer ? b2    : b1;

        gat_gemm_attn_kernel<<<(NN + 63) / 64, 128, GSMEM>>>(W, asrc, adst, layer);
        gat_agg_kernel<<<(NN * 32 + 255) / 256, 256>>>(bb, Wh, bh, out, layer);
    }
}

// round 14
// speedup vs baseline: 1.1173x; 1.0367x over previous
#include <cuda_runtime.h>
#include <cuda_fp16.h>
#include <math.h>
#include <stdint.h>

// ---------------- problem constants ------------------------------------------
#define NN      20000
#define TT      60
#define DDIM    20
#define HH      128
#define GGDIM   128
#define NHEADS  4
#define CCH     32
#define EE      320000
#define ETOT    (EE + NN)
#define G4      512
#define LNODES  144
#define MTILES  9
#define LGRID   139
#define GSTR    (LGRID * LNODES)
#define LTHR    512

#define KXP     40
#define KHP     136
#define AXE     (LNODES * DDIM)

// ---------------- LSTM smem layout (bytes) -----------------------------------
#define OFF_AH1  0
#define OFF_WX   0
#define OFF_WH   40960
#define OFF_AX   172032
#define OFF_AH0  183552
#define OFF_BIAS 222720
#define SMEM_TOTAL 224768

// ---------------- GAT gemm+attn smem layout (bytes, dynamic) ------------------
#define GOFF_A   0
#define GOFF_B   16384
#define GOFF_AS  49152
#define GOFF_AD  49664
#define GSMEM    50176

// ---------------- scratch (device globals) ------------------------------------
__device__ float g_h[GSTR * HH];
__device__ float g_xh[NN * GGDIM];
__device__ float g_feat[NN * GGDIM];
__device__ float g_asr[NN * NHEADS];
__device__ float g_adt[NN * NHEADS];
__device__ int   g_cnt[NN];          // loader-zeroed; re-zeroed by scan each call
__device__ int   g_row[NN + 1];
__device__ int   g_cur[NN];
__device__ int   g_csr[ETOT];

// ---------------- helpers -----------------------------------------------------
__device__ __forceinline__ float tanhapx(float x) {
    float y; asm("tanh.approx.f32 %0, %1;" : "=f"(y) : "f"(x)); return y;
}
__device__ __forceinline__ float sigt(float x) {
    return fmaf(tanhapx(0.5f * x), 0.5f, 0.5f);
}
__device__ __forceinline__ void mma16816(float* d,
                                         uint32_t a0, uint32_t a1, uint32_t a2, uint32_t a3,
                                         uint32_t b0, uint32_t b1) {
    asm volatile(
        "mma.sync.aligned.m16n8k16.row.col.f32.f16.f16.f32 "
        "{%0,%1,%2,%3}, {%4,%5,%6,%7}, {%8,%9}, {%0,%1,%2,%3};"
        : "+f"(d[0]), "+f"(d[1]), "+f"(d[2]), "+f"(d[3])
        : "r"(a0), "r"(a1), "r"(a2), "r"(a3), "r"(b0), "r"(b1));
}
__device__ __forceinline__ void ldm_x4(uint32_t addr, uint32_t* r) {
    asm volatile("ldmatrix.sync.aligned.m8n8.x4.shared.b16 {%0,%1,%2,%3}, [%4];"
                 : "=r"(r[0]), "=r"(r[1]), "=r"(r[2]), "=r"(r[3]) : "r"(addr));
}
__device__ __forceinline__ float lrelu(float v) { return v > 0.0f ? v : 0.2f * v; }

// gate-column permutation: n' = warp*32 + gate*8 + jloc
//   orig gate row = gate*128 + (warp*8 + jloc)
__device__ __forceinline__ int perm_row(int n) {
    return ((n >> 3) & 3) * HH + ((n >> 5) * 8 + (n & 7));
}

// ---------------- persistent LSTM kernel (shfl-free epilogue) -----------------
__global__ __launch_bounds__(LTHR, 1) void lstm_all_kernel(
    const float* __restrict__ x,
    const float* __restrict__ Wih, const float* __restrict__ Whh,
    const float* __restrict__ bih, const float* __restrict__ bhh)
{
    extern __shared__ char smem[];
    __half* WX = (__half*)(smem + OFF_WX);
    __half* AX = (__half*)(smem + OFF_AX);
    float*  sbias = (float*)(smem + OFF_BIAS);
    const uint32_t sWX  = (uint32_t)__cvta_generic_to_shared(smem + OFF_WX);
    const uint32_t sWH  = (uint32_t)__cvta_generic_to_shared(smem + OFF_WH);
    const uint32_t sAX  = (uint32_t)__cvta_generic_to_shared(smem + OFF_AX);
    const uint32_t sAH0 = (uint32_t)__cvta_generic_to_shared(smem + OFF_AH0);
    const uint32_t sAH1 = (uint32_t)__cvta_generic_to_shared(smem + OFF_AH1);

    const int tid = threadIdx.x;
    const int blk = blockIdx.x;

    for (int i = tid; i < OFF_BIAS / 4; i += LTHR) ((uint32_t*)smem)[i] = 0;
    __syncthreads();

    for (int i = tid; i < G4 * DDIM; i += LTHR) {
        int n = i / DDIM, k = i - n * DDIM;
        int row = perm_row(n);
        WX[n * KXP + k] = __float2half_rn(Wih[row * DDIM + k]);
    }
    for (int i = tid; i < G4 * HH; i += LTHR) {
        int n = i >> 7, k = i & 127;
        int row = perm_row(n);
        uint32_t byte = (uint32_t)(n * 256 + ((((k >> 3) ^ (n & 7)) << 4)) + ((k & 7) << 1));
        *(__half*)(smem + OFF_WH + byte) = __float2half_rn(Whh[row * HH + k]);
    }
    for (int i = tid; i < G4; i += LTHR) {
        int row = perm_row(i);
        sbias[i] = bih[row] + bhh[row];
    }
    __syncthreads();

    const int wid  = tid >> 5;
    const int lane = tid & 31;
    const int g    = lane >> 2;
    const int cc   = lane & 3;
    const int n0   = wid * 32;
    const int j0   = (wid << 3) + 2 * cc;    // this thread's cell pair

    const int sub = lane >> 3, rr = lane & 7;
    const int arow = (sub & 1) * 8 + rr;
    const int akof = (sub >> 1) * 8;
    const int bcol = rr + ((sub >> 1) * 8);
    const int bkof = (sub & 1) * 8;
    const uint32_t laneAH = (uint32_t)(arow * KHP + akof) * 2;
    const uint32_t axb  = sAX  + (uint32_t)(arow * KXP + akof) * 2;
    const uint32_t ahb0 = sAH0 + laneAH;
    const uint32_t ahb1 = sAH1 + laneAH;
    const uint32_t xorv = (uint32_t)(rr << 4);
    uint32_t wxb[2], whb[2];
#pragma unroll
    for (int np = 0; np < 2; ++np) {
        wxb[np] = sWX + (uint32_t)((n0 + np * 16 + bcol) * KXP + bkof) * 2;
        whb[np] = sWH + (uint32_t)(n0 + np * 16 + bcol) * 256;
    }
    const uint32_t bko2 = (uint32_t)(bkof << 1);

    float bias0[4], bias1[4];
#pragma unroll
    for (int nt = 0; nt < 4; ++nt) {           // nt == gate
        bias0[nt] = sbias[n0 + nt * 8 + 2 * cc];
        bias1[nt] = sbias[n0 + nt * 8 + 2 * cc + 1];
    }

    uint32_t bxf[2][2][4];
#pragma unroll
    for (int ks = 0; ks < 2; ++ks)
#pragma unroll
        for (int np = 0; np < 2; ++np)
            ldm_x4(wxb[np] + (uint32_t)(ks * 32), bxf[ks][np]);

    float creg[MTILES][4];
#pragma unroll
    for (int mt = 0; mt < MTILES; ++mt)
#pragma unroll
        for (int nt = 0; nt < 4; ++nt) creg[mt][nt] = 0.0f;

    __syncthreads();

    for (int s = 0; s < TT; ++s) {
        for (int i = tid; i < AXE; i += LTHR) {
            int mm = i / DDIM, k = i - mm * DDIM;
            int n = blk * LNODES + mm;
            AX[mm * KXP + k] = __float2half_rn(n < NN ? x[n * (TT * DDIM) + s * DDIM + k] : 0.0f);
        }
        __syncthreads();

        const bool last = (s == TT - 1);
        const uint32_t ahb_r = (s & 1) ? ahb1 : ahb0;
        __half* AHW = (__half*)(smem + ((s & 1) ? OFF_AH0 : OFF_AH1));

        // shfl-free epilogue: acc[gate][z], z = {row g: cells j0, j0+1; row g+8: ...}
        auto epilogue = [&](int mt, float (&acc)[4][4]) {
#pragma unroll
            for (int hf = 0; hf < 2; ++hf) {
                const int row = mt * 16 + g + hf * 8;
                float hv[2];
#pragma unroll
                for (int b = 0; b < 2; ++b) {
                    const int z = hf * 2 + b;
                    float gi = acc[0][z], gf = acc[1][z];
                    float gg = acc[2][z], go = acc[3][z];
                    float cold = creg[mt][z];
                    float cn = sigt(gf) * cold + sigt(gi) * tanhapx(gg);
                    creg[mt][z] = cn;
                    hv[b] = sigt(go) * tanhapx(cn);
                }
                *(__half2*)&AHW[row * KHP + j0] = __floats2half2_rn(hv[0], hv[1]);
                if (last)
                    *(float2*)&g_h[(blk * LNODES + row) * HH + j0] = make_float2(hv[0], hv[1]);
            }
        };

#pragma unroll
        for (int p = 0; p < 5; ++p) {
            const int m0 = 2 * p;
            const bool has1 = (m0 + 1 < MTILES);

            float acc0[4][4], acc1[4][4];
#pragma unroll
            for (int nt = 0; nt < 4; ++nt) {
                acc0[nt][0] = bias0[nt]; acc0[nt][1] = bias1[nt];
                acc0[nt][2] = bias0[nt]; acc0[nt][3] = bias1[nt];
                acc1[nt][0] = bias0[nt]; acc1[nt][1] = bias1[nt];
                acc1[nt][2] = bias0[nt]; acc1[nt][3] = bias1[nt];
            }
#pragma unroll
            for (int ks = 0; ks < 2; ++ks) {
                uint32_t a[4];
                ldm_x4(axb + (uint32_t)(m0 * 16 * (KXP * 2) + ks * 32), a);
#pragma unroll
                for (int np = 0; np < 2; ++np) {
                    mma16816(acc0[2 * np],     a[0], a[1], a[2], a[3], bxf[ks][np][0], bxf[ks][np][1]);
                    mma16816(acc0[2 * np + 1], a[0], a[1], a[2], a[3], bxf[ks][np][2], bxf[ks][np][3]);
                }
                if (has1) {
                    uint32_t a1[4];
                    ldm_x4(axb + (uint32_t)((m0 + 1) * 16 * (KXP * 2) + ks * 32), a1);
#pragma unroll
                    for (int np = 0; np < 2; ++np) {
                        mma16816(acc1[2 * np],     a1[0], a1[1], a1[2], a1[3], bxf[ks][np][0], bxf[ks][np][1]);
                        mma16816(acc1[2 * np + 1], a1[0], a1[1], a1[2], a1[3], bxf[ks][np][2], bxf[ks][np][3]);
                    }
                }
            }
#pragma unroll
            for (int ks = 0; ks < 8; ++ks) {
                uint32_t b0[4], b1[4];
                ldm_x4(whb[0] + (((uint32_t)(ks * 32) + bko2) ^ xorv), b0);
                ldm_x4(whb[1] + (((uint32_t)(ks * 32) + bko2) ^ xorv), b1);
                uint32_t a[4];
                ldm_x4(ahb_r + (uint32_t)(m0 * 16 * (KHP * 2) + ks * 32), a);
                mma16816(acc0[0], a[0], a[1], a[2], a[3], b0[0], b0[1]);
                mma16816(acc0[1], a[0], a[1], a[2], a[3], b0[2], b0[3]);
                mma16816(acc0[2], a[0], a[1], a[2], a[3], b1[0], b1[1]);
                mma16816(acc0[3], a[0], a[1], a[2], a[3], b1[2], b1[3]);
                if (has1) {
                    uint32_t a1[4];
                    ldm_x4(ahb_r + (uint32_t)((m0 + 1) * 16 * (KHP * 2) + ks * 32), a1);
                    mma16816(acc1[0], a1[0], a1[1], a1[2], a1[3], b0[0], b0[1]);
                    mma16816(acc1[1], a1[0], a1[1], a1[2], a1[3], b0[2], b0[3]);
                    mma16816(acc1[2], a1[0], a1[1], a1[2], a1[3], b1[0], b1[1]);
                    mma16816(acc1[3], a1[0], a1[1], a1[2], a1[3], b1[2], b1[3]);
                }
            }

            epilogue(m0, acc0);
            if (has1) epilogue(m0 + 1, acc1);
        }
        __syncthreads();
    }
}

// ---------------- CSR build ----------------------------------------------------
__global__ void csr_count_kernel(const int* __restrict__ ei) {
    int e = blockIdx.x * blockDim.x + threadIdx.x;
    if (e >= ETOT) return;
    int d = (e < EE) ? ei[EE + e] : (e - EE);
    atomicAdd(&g_cnt[d], 1);
}
__global__ __launch_bounds__(1024) void csr_scan_kernel() {
    __shared__ int swarp[32];
    const int t = threadIdx.x;
    const int lane = t & 31, wid = t >> 5;
    const int ITEMS = (NN + 1023) / 1024;
    const int base = t * ITEMS;

    int c[ITEMS];
    int total = 0;
#pragma unroll
    for (int i = 0; i < ITEMS; ++i) {
        int idx = base + i;
        c[i] = (idx < NN) ? g_cnt[idx] : 0;
        total += c[i];
        if (idx < NN) g_cnt[idx] = 0;
    }
    int incl = total;
#pragma unroll
    for (int o = 1; o < 32; o <<= 1) {
        int v = __shfl_up_sync(0xffffffffu, incl, o);
        if (lane >= o) incl += v;
    }
    if (lane == 31) swarp[wid] = incl;
    __syncthreads();
    if (wid == 0) {
        int w = swarp[lane];
        int wi = w;
#pragma unroll
        for (int o = 1; o < 32; o <<= 1) {
            int v = __shfl_up_sync(0xffffffffu, wi, o);
            if (lane >= o) wi += v;
        }
        swarp[lane] = wi - w;
    }
    __syncthreads();
    int run = swarp[wid] + (incl - total);
#pragma unroll
    for (int i = 0; i < ITEMS; ++i) {
        int idx = base + i;
        if (idx < NN) {
            g_row[idx] = run;
            g_cur[idx] = run;
            run += c[i];
        }
    }
    if (t == 1023) g_row[NN] = run;
}
__global__ void csr_scatter_kernel(const int* __restrict__ ei) {
    int e = blockIdx.x * blockDim.x + threadIdx.x;
    if (e >= ETOT) return;
    int s, d;
    if (e < EE) { s = ei[e]; d = ei[EE + e]; } else { s = e - EE; d = s; }
    int pos = atomicAdd(&g_cur[d], 1);
    g_csr[pos] = s;
}

// ---------------- fused GAT dense: xh = X@W (HMMA) + attn dots ----------------
__global__ __launch_bounds__(128) void gat_gemm_attn_kernel(
    const float* __restrict__ W, const float* __restrict__ a_src,
    const float* __restrict__ a_dst, int layer)
{
    const float* __restrict__ X = (layer == 0) ? g_h : g_feat;
    extern __shared__ char smem[];
    float* sas = (float*)(smem + GOFF_AS);
    float* sad = (float*)(smem + GOFF_AD);
    const uint32_t sA = (uint32_t)__cvta_generic_to_shared(smem + GOFF_A);
    const uint32_t sB = (uint32_t)__cvta_generic_to_shared(smem + GOFF_B);

    const int tid = threadIdx.x;
    const int n64 = blockIdx.x * 64;

    for (int i = tid; i < 64 * 128; i += 128) {
        int r = i >> 7, k = i & 127;
        float v = (n64 + r < NN) ? X[(n64 + r) * GGDIM + k] : 0.0f;
        uint32_t byte = (uint32_t)(r * 256 + (((k >> 3) ^ (r & 7)) << 4) + ((k & 7) << 1));
        *(__half*)(smem + GOFF_A + byte) = __float2half_rn(v);
    }
    for (int i = tid; i < 128 * 128; i += 128) {
        int n = i >> 7, k = i & 127;
        uint32_t byte = (uint32_t)(n * 256 + (((k >> 3) ^ (n & 7)) << 4) + ((k & 7) << 1));
        *(__half*)(smem + GOFF_B + byte) = __float2half_rn(W[k * GGDIM + n]);
    }
    if (tid < 128) { sas[tid] = a_src[tid]; sad[tid] = a_dst[tid]; }
    __syncthreads();

    const int wid  = tid >> 5;
    const int lane = tid & 31;
    const int g    = lane >> 2;
    const int cc   = lane & 3;
    const int sub = lane >> 3, rr = lane & 7;
    const int arow = (sub & 1) * 8 + rr;
    const int akof = (sub >> 1) * 8;
    const int bcol = rr + ((sub >> 1) * 8);
    const int bkof = (sub & 1) * 8;
    const uint32_t xorv = (uint32_t)(rr << 4);
    const uint32_t ako2 = (uint32_t)(akof << 1);
    const uint32_t bko2 = (uint32_t)(bkof << 1);
    const uint32_t arowb = sA + (uint32_t)(wid * 16 + arow) * 256;

    float acc[16][4];
#pragma unroll
    for (int q = 0; q < 16; ++q)
#pragma unroll
        for (int z = 0; z < 4; ++z) acc[q][z] = 0.0f;

#pragma unroll
    for (int ks = 0; ks < 8; ++ks) {
        uint32_t a[4];
        ldm_x4(arowb + (((uint32_t)(ks * 32) + ako2) ^ xorv), a);
#pragma unroll
        for (int np = 0; np < 8; ++np) {
            uint32_t b[4];
            ldm_x4(sB + (uint32_t)(np * 16 + bcol) * 256 + (((uint32_t)(ks * 32) + bko2) ^ xorv), b);
            mma16816(acc[2 * np],     a[0], a[1], a[2], a[3], b[0], b[1]);
            mma16816(acc[2 * np + 1], a[0], a[1], a[2], a[3], b[2], b[3]);
        }
    }

    const int gr0 = n64 + wid * 16 + g;
    const int gr1 = gr0 + 8;
#pragma unroll
    for (int np = 0; np < 8; ++np) {
        int c0 = np * 16 + 2 * cc, c1 = np * 16 + 8 + 2 * cc;
        if (gr0 < NN) {
            *(float2*)&g_xh[gr0 * GGDIM + c0] = make_float2(acc[2 * np][0], acc[2 * np][1]);
            *(float2*)&g_xh[gr0 * GGDIM + c1] = make_float2(acc[2 * np + 1][0], acc[2 * np + 1][1]);
        }
        if (gr1 < NN) {
            *(float2*)&g_xh[gr1 * GGDIM + c0] = make_float2(acc[2 * np][2], acc[2 * np][3]);
            *(float2*)&g_xh[gr1 * GGDIM + c1] = make_float2(acc[2 * np + 1][2], acc[2 * np + 1][3]);
        }
    }

    float rs0[4], rs1[4], rd0[4], rd1[4];
#pragma unroll
    for (int h = 0; h < 4; ++h) {
        float s0 = 0.0f, s1 = 0.0f, d0 = 0.0f, d1 = 0.0f;
#pragma unroll
        for (int tti = 0; tti < 4; ++tti) {
            int np = h * 2 + (tti >> 1);
            int ai = 2 * np + (tti & 1);
            int col = np * 16 + (tti & 1) * 8 + 2 * cc;
            float w0s = sas[col], w1s = sas[col + 1];
            float w0d = sad[col], w1d = sad[col + 1];
            s0 += acc[ai][0] * w0s + acc[ai][1] * w1s;
            s1 += acc[ai][2] * w0s + acc[ai][3] * w1s;
            d0 += acc[ai][0] * w0d + acc[ai][1] * w1d;
            d1 += acc[ai][2] * w0d + acc[ai][3] * w1d;
        }
        s0 += __shfl_xor_sync(0xffffffffu, s0, 1); s0 += __shfl_xor_sync(0xffffffffu, s0, 2);
        s1 += __shfl_xor_sync(0xffffffffu, s1, 1); s1 += __shfl_xor_sync(0xffffffffu, s1, 2);
        d0 += __shfl_xor_sync(0xffffffffu, d0, 1); d0 += __shfl_xor_sync(0xffffffffu, d0, 2);
        d1 += __shfl_xor_sync(0xffffffffu, d1, 1); d1 += __shfl_xor_sync(0xffffffffu, d1, 2);
        rs0[h] = s0; rs1[h] = s1; rd0[h] = d0; rd1[h] = d1;
    }
    if (gr0 < NN) { g_asr[gr0 * 4 + cc] = rs0[cc]; g_adt[gr0 * 4 + cc] = rd0[cc]; }
    if (gr1 < NN) { g_asr[gr1 * 4 + cc] = rs1[cc]; g_adt[gr1 * 4 + cc] = rd1[cc]; }
}

// -------- fused softmax + aggregate + bias + ELU (+ optional head) ------------
__global__ __launch_bounds__(256) void gat_agg_kernel(
    const float* __restrict__ bias, const float* __restrict__ Wh,
    const float* __restrict__ bh, float* __restrict__ out, int last)
{
    const int d    = (blockIdx.x * 256 + threadIdx.x) >> 5;
    const int lane = threadIdx.x & 31;
    if (d >= NN) return;
    const int start = g_row[d], end = g_row[d + 1];

    const float4 adt4 = *(const float4*)&g_adt[d * 4];

    float s0 = 0.0f, s1 = 0.0f, s2 = 0.0f, s3 = 0.0f;
    for (int idx = start + lane; idx < end; idx += 32) {
        int s = g_csr[idx];
        float4 a = *(const float4*)&g_asr[s * 4];
        s0 += __expf(lrelu(a.x + adt4.x));
        s1 += __expf(lrelu(a.y + adt4.y));
        s2 += __expf(lrelu(a.z + adt4.z));
        s3 += __expf(lrelu(a.w + adt4.w));
    }
#pragma unroll
    for (int off = 16; off > 0; off >>= 1) {
        s0 += __shfl_xor_sync(0xffffffffu, s0, off);
        s1 += __shfl_xor_sync(0xffffffffu, s1, off);
        s2 += __shfl_xor_sync(0xffffffffu, s2, off);
        s3 += __shfl_xor_sync(0xffffffffu, s3, off);
    }

    const int head = lane >> 3;
    float adt_h, den_h;
    if (head == 0)      { adt_h = adt4.x; den_h = s0; }
    else if (head == 1) { adt_h = adt4.y; den_h = s1; }
    else if (head == 2) { adt_h = adt4.z; den_h = s2; }
    else                { adt_h = adt4.w; den_h = s3; }
    const float inv_den = 1.0f / (den_h + 1e-16f);

    float4 acc = make_float4(0.0f, 0.0f, 0.0f, 0.0f);
    for (int idx = start; idx < end; ++idx) {
        int s = g_csr[idx];
        float as_h = g_asr[s * 4 + head];
        float alpha = __expf(lrelu(as_h + adt_h)) * inv_den;
        float4 xv = *(const float4*)&g_xh[s * GGDIM + lane * 4];
        acc.x = fmaf(alpha, xv.x, acc.x);
        acc.y = fmaf(alpha, xv.y, acc.y);
        acc.z = fmaf(alpha, xv.z, acc.z);
        acc.w = fmaf(alpha, xv.w, acc.w);
    }

    const float4 bv = *(const float4*)&bias[lane * 4];
    float4 outv;
    float v;
    v = acc.x + bv.x; outv.x = v > 0.0f ? v : (__expf(v) - 1.0f);
    v = acc.y + bv.y; outv.y = v > 0.0f ? v : (__expf(v) - 1.0f);
    v = acc.z + bv.z; outv.z = v > 0.0f ? v : (__expf(v) - 1.0f);
    v = acc.w + bv.w; outv.w = v > 0.0f ? v : (__expf(v) - 1.0f);

    if (!last) {
        *(float4*)&g_feat[d * GGDIM + lane * 4] = outv;
    } else {
        int ch = lane * 4;
        float p0 = outv.x * Wh[2 * ch + 0] + outv.y * Wh[2 * ch + 2]
                 + outv.z * Wh[2 * ch + 4] + outv.w * Wh[2 * ch + 6];
        float p1 = outv.x * Wh[2 * ch + 1] + outv.y * Wh[2 * ch + 3]
                 + outv.z * Wh[2 * ch + 5] + outv.w * Wh[2 * ch + 7];
#pragma unroll
        for (int off = 16; off > 0; off >>= 1) {
            p0 += __shfl_xor_sync(0xffffffffu, p0, off);
            p1 += __shfl_xor_sync(0xffffffffu, p1, off);
        }
        if (lane == 0) {
            out[2 * d + 0] = p0 + bh[0];
            out[2 * d + 1] = p1 + bh[1];
        }
    }
}

// ---------------- launch --------------------------------------------------------
extern "C" void kernel_launch(void* const* d_in, const int* in_sizes, int n_in,
                              void* d_out, int out_size) {
    const float* x_win  = (const float*)d_in[0];
    const int*   ei     = (const int*)  d_in[1];
    const float* Wih    = (const float*)d_in[2];
    const float* Whh    = (const float*)d_in[3];
    const float* bih    = (const float*)d_in[4];
    const float* bhh    = (const float*)d_in[5];
    const float* W1     = (const float*)d_in[6];
    const float* asrc1  = (const float*)d_in[7];
    const float* adst1  = (const float*)d_in[8];
    const float* b1     = (const float*)d_in[9];
    const float* W2     = (const float*)d_in[10];
    const float* asrc2  = (const float*)d_in[11];
    const float* adst2  = (const float*)d_in[12];
    const float* b2     = (const float*)d_in[13];
    const float* Wh     = (const float*)d_in[14];
    const float* bh     = (const float*)d_in[15];
    float* out = (float*)d_out;

    static cudaStream_t s_aux = nullptr;
    static cudaEvent_t  ev_fork = nullptr, ev_join = nullptr;
    static bool attr_done = false;
    if (!attr_done) {
        cudaFuncSetAttribute(lstm_all_kernel,
                             cudaFuncAttributeMaxDynamicSharedMemorySize, SMEM_TOTAL);
        cudaFuncSetAttribute(gat_gemm_attn_kernel,
                             cudaFuncAttributeMaxDynamicSharedMemorySize, GSMEM);
        cudaStreamCreateWithFlags(&s_aux, cudaStreamNonBlocking);
        cudaEventCreateWithFlags(&ev_fork, cudaEventDisableTiming);
        cudaEventCreateWithFlags(&ev_join, cudaEventDisableTiming);
        attr_done = true;
    }

    // fork: CSR build runs concurrently with the LSTM (independent inputs)
    cudaEventRecord(ev_fork, 0);
    cudaStreamWaitEvent(s_aux, ev_fork, 0);

    lstm_all_kernel<<<LGRID, LTHR, SMEM_TOTAL>>>(x_win, Wih, Whh, bih, bhh);

    csr_count_kernel<<<(ETOT + 255) / 256, 256, 0, s_aux>>>(ei);
    csr_scan_kernel<<<1, 1024, 0, s_aux>>>();
    csr_scatter_kernel<<<(ETOT + 255) / 256, 256, 0, s_aux>>>(ei);
    cudaEventRecord(ev_join, s_aux);
    cudaStreamWaitEvent(0, ev_join, 0);

    for (int layer = 0; layer < 2; layer++) {
        const float* W    = layer ? W2    : W1;
        const float* asrc = layer ? asrc2 : asrc1;
        const float* adst = layer ? adst2 : adst1;
        const float* bb   = layer ? b2    : b1;

        gat_gemm_attn_kernel<<<(NN + 63) / 64, 128, GSMEM>>>(W, asrc, adst, layer);
        gat_agg_kernel<<<(NN * 32 + 255) / 256, 256>>>(bb, Wh, bh, out, layer);
    }
}

// round 15
// speedup vs baseline: 1.2194x; 1.0914x over previous
#include <cuda_runtime.h>
#include <cuda_fp16.h>
#include <math.h>
#include <stdint.h>

// ---------------- problem constants ------------------------------------------
#define NN      20000
#define TT      60
#define DDIM    20
#define HH      128
#define GGDIM   128
#define NHEADS  4
#define CCH     32
#define EE      320000
#define ETOT    (EE + NN)
#define G4      512
#define LNODES  144
#define MTILES  9
#define LGRID   139
#define GSTR    (LGRID * LNODES)
#define LTHR    512

#define KXP     40                  // AX row stride in halves (80B, conflict-free)
#define AXE     (LNODES * DDIM)

// ---------------- LSTM smem layout (bytes) -----------------------------------
// AH buffers use 256B swizzled rows (same scheme as WH). WX staged in the AH1
// region during init only (bxf hoisted to registers before AH1/AX0 are touched).
#define OFF_WH   0                          // 512 x 256B swizzled   (131072)
#define OFF_AH0  131072                     // 144 x 256B swizzled   (36864)
#define OFF_AH1  167936                     // 144 x 256B swizzled   (36864)
#define OFF_WX   167936                     // init-only overlay     (40960)
#define OFF_AX0  204800                     // 144 x 40 f16          (11520)
#define OFF_AX1  216320                     // 144 x 40 f16          (11520)
#define OFF_BIAS 227840                     // 512 f32               (2048)
#define SMEM_TOTAL 229888

// ---------------- GAT gemm+attn smem layout (bytes, dynamic) ------------------
#define GOFF_A   0
#define GOFF_B   16384
#define GOFF_AS  49152
#define GOFF_AD  49664
#define GSMEM    50176

// ---------------- scratch (device globals) ------------------------------------
__device__ float g_h[GSTR * HH];
__device__ float g_xh[NN * GGDIM];
__device__ float g_feat[NN * GGDIM];
__device__ float g_asr[NN * NHEADS];
__device__ float g_adt[NN * NHEADS];
__device__ int   g_cnt[NN];          // loader-zeroed; re-zeroed by scan each call
__device__ int   g_row[NN + 1];
__device__ int   g_cur[NN];
__device__ int   g_csr[ETOT];

// ---------------- helpers -----------------------------------------------------
__device__ __forceinline__ float tanhapx(float x) {
    float y; asm("tanh.approx.f32 %0, %1;" : "=f"(y) : "f"(x)); return y;
}
__device__ __forceinline__ float sigt(float x) {
    return fmaf(tanhapx(0.5f * x), 0.5f, 0.5f);
}
__device__ __forceinline__ void mma16816(float* d,
                                         uint32_t a0, uint32_t a1, uint32_t a2, uint32_t a3,
                                         uint32_t b0, uint32_t b1) {
    asm volatile(
        "mma.sync.aligned.m16n8k16.row.col.f32.f16.f16.f32 "
        "{%0,%1,%2,%3}, {%4,%5,%6,%7}, {%8,%9}, {%0,%1,%2,%3};"
        : "+f"(d[0]), "+f"(d[1]), "+f"(d[2]), "+f"(d[3])
        : "r"(a0), "r"(a1), "r"(a2), "r"(a3), "r"(b0), "r"(b1));
}
__device__ __forceinline__ void ldm_x4(uint32_t addr, uint32_t* r) {
    asm volatile("ldmatrix.sync.aligned.m8n8.x4.shared.b16 {%0,%1,%2,%3}, [%4];"
                 : "=r"(r[0]), "=r"(r[1]), "=r"(r[2]), "=r"(r[3]) : "r"(addr));
}
__device__ __forceinline__ float lrelu(float v) { return v > 0.0f ? v : 0.2f * v; }

// gate-column permutation: n' = warp*32 + gate*8 + jloc
__device__ __forceinline__ int perm_row(int n) {
    return ((n >> 3) & 3) * HH + ((n >> 5) * 8 + (n & 7));
}

// ---------------- persistent LSTM kernel (1 barrier/step, dbl-buffered AX/AH) -
__global__ __launch_bounds__(LTHR, 1) void lstm_all_kernel(
    const float* __restrict__ x,
    const float* __restrict__ Wih, const float* __restrict__ Whh,
    const float* __restrict__ bih, const float* __restrict__ bhh)
{
    extern __shared__ char smem[];
    __half* WX = (__half*)(smem + OFF_WX);
    float*  sbias = (float*)(smem + OFF_BIAS);
    const uint32_t sWX  = (uint32_t)__cvta_generic_to_shared(smem + OFF_WX);
    const uint32_t sWH  = (uint32_t)__cvta_generic_to_shared(smem + OFF_WH);
    const uint32_t sAX0 = (uint32_t)__cvta_generic_to_shared(smem + OFF_AX0);
    const uint32_t sAX1 = (uint32_t)__cvta_generic_to_shared(smem + OFF_AX1);
    const uint32_t sAH0 = (uint32_t)__cvta_generic_to_shared(smem + OFF_AH0);
    const uint32_t sAH1 = (uint32_t)__cvta_generic_to_shared(smem + OFF_AH1);

    const int tid = threadIdx.x;
    const int blk = blockIdx.x;

    for (int i = tid; i < SMEM_TOTAL / 4; i += LTHR) ((uint32_t*)smem)[i] = 0;
    __syncthreads();

    // ---- stage weights (WX overlays AH1/AX0-start; used only for bxf hoist) --
    for (int i = tid; i < G4 * DDIM; i += LTHR) {
        int n = i / DDIM, k = i - n * DDIM;
        int row = perm_row(n);
        WX[n * KXP + k] = __float2half_rn(Wih[row * DDIM + k]);
    }
    for (int i = tid; i < G4 * HH; i += LTHR) {
        int n = i >> 7, k = i & 127;
        int row = perm_row(n);
        uint32_t byte = (uint32_t)(n * 256 + ((((k >> 3) ^ (n & 7)) << 4)) + ((k & 7) << 1));
        *(__half*)(smem + OFF_WH + byte) = __float2half_rn(Whh[row * HH + k]);
    }
    for (int i = tid; i < G4; i += LTHR) {
        int row = perm_row(i);
        sbias[i] = bih[row] + bhh[row];
    }
    __syncthreads();

    const int wid  = tid >> 5;
    const int lane = tid & 31;
    const int g    = lane >> 2;
    const int cc   = lane & 3;
    const int n0   = wid * 32;
    const int j0   = (wid << 3) + 2 * cc;    // this thread's cell pair

    const int sub = lane >> 3, rr = lane & 7;
    const int arow = (sub & 1) * 8 + rr;
    const int akof = (sub >> 1) * 8;
    const int bcol = rr + ((sub >> 1) * 8);
    const int bkof = (sub & 1) * 8;
    const uint32_t axb0 = sAX0 + (uint32_t)(arow * KXP + akof) * 2;
    const uint32_t axb1 = sAX1 + (uint32_t)(arow * KXP + akof) * 2;
    const uint32_t ahbase0 = sAH0 + (uint32_t)arow * 256;
    const uint32_t ahbase1 = sAH1 + (uint32_t)arow * 256;
    const uint32_t xorv = (uint32_t)(rr << 4);
    const uint32_t ako2 = (uint32_t)(akof << 1);   // 0 or 16
    const uint32_t bko2 = (uint32_t)(bkof << 1);
    const uint32_t ahw_off = (uint32_t)(((wid ^ g) << 4) + 4 * cc);  // epilogue store
    uint32_t wxb[2], whb[2];
#pragma unroll
    for (int np = 0; np < 2; ++np) {
        wxb[np] = sWX + (uint32_t)((n0 + np * 16 + bcol) * KXP + bkof) * 2;
        whb[np] = sWH + (uint32_t)(n0 + np * 16 + bcol) * 256;
    }

    float bias0[4], bias1[4];
#pragma unroll
    for (int nt = 0; nt < 4; ++nt) {           // nt == gate
        bias0[nt] = sbias[n0 + nt * 8 + 2 * cc];
        bias1[nt] = sbias[n0 + nt * 8 + 2 * cc + 1];
    }

    uint32_t bxf[2][2][4];
#pragma unroll
    for (int ks = 0; ks < 2; ++ks)
#pragma unroll
        for (int np = 0; np < 2; ++np)
            ldm_x4(wxb[np] + (uint32_t)(ks * 32), bxf[ks][np]);

    float creg[MTILES][4];
#pragma unroll
    for (int mt = 0; mt < MTILES; ++mt)
#pragma unroll
        for (int nt = 0; nt < 4; ++nt) creg[mt][nt] = 0.0f;

    __syncthreads();   // all bxf reads done before AX0 (overlapping WX) is written

    // prefill AX0 (step 0)
    {
        __half* AX = (__half*)(smem + OFF_AX0);
        for (int i = tid; i < AXE; i += LTHR) {
            int mm = i / DDIM, k = i - mm * DDIM;
            int n = blk * LNODES + mm;
            AX[mm * KXP + k] = __float2half_rn(n < NN ? x[n * (TT * DDIM) + 0 * DDIM + k] : 0.0f);
        }
    }

    for (int s = 0; s < TT; ++s) {
        __syncthreads();   // AX(s) + AH(s) ready; prev-step reads complete

        // prefetch AX(s+1) into the other buffer (overlaps GEMM below)
        if (s + 1 < TT) {
            __half* AXN = (__half*)(smem + (((s + 1) & 1) ? OFF_AX1 : OFF_AX0));
            for (int i = tid; i < AXE; i += LTHR) {
                int mm = i / DDIM, k = i - mm * DDIM;
                int n = blk * LNODES + mm;
                AXN[mm * KXP + k] = __float2half_rn(n < NN ? x[n * (TT * DDIM) + (s + 1) * DDIM + k] : 0.0f);
            }
        }

        const bool last = (s == TT - 1);
        const uint32_t axb_r = (s & 1) ? axb1 : axb0;
        const uint32_t ahb_r = (s & 1) ? ahbase1 : ahbase0;
        char* AHWc = smem + ((s & 1) ? OFF_AH0 : OFF_AH1);   // write buffer

        auto epilogue = [&](int mt, float (&acc)[4][4]) {
#pragma unroll
            for (int hf = 0; hf < 2; ++hf) {
                const int row = mt * 16 + g + hf * 8;
                float hv[2];
#pragma unroll
                for (int b = 0; b < 2; ++b) {
                    const int z = hf * 2 + b;
                    float gi = acc[0][z], gf = acc[1][z];
                    float gg = acc[2][z], go = acc[3][z];
                    float cold = creg[mt][z];
                    float cn = sigt(gf) * cold + sigt(gi) * tanhapx(gg);
                    creg[mt][z] = cn;
                    hv[b] = sigt(go) * tanhapx(cn);
                }
                *(__half2*)(AHWc + (uint32_t)row * 256 + ahw_off) = __floats2half2_rn(hv[0], hv[1]);
                if (last)
                    *(float2*)&g_h[(blk * LNODES + row) * HH + j0] = make_float2(hv[0], hv[1]);
            }
        };

#pragma unroll
        for (int p = 0; p < 5; ++p) {
            const int m0 = 2 * p;
            const bool has1 = (m0 + 1 < MTILES);

            float acc0[4][4], acc1[4][4];
#pragma unroll
            for (int nt = 0; nt < 4; ++nt) {
                acc0[nt][0] = bias0[nt]; acc0[nt][1] = bias1[nt];
                acc0[nt][2] = bias0[nt]; acc0[nt][3] = bias1[nt];
                acc1[nt][0] = bias0[nt]; acc1[nt][1] = bias1[nt];
                acc1[nt][2] = bias0[nt]; acc1[nt][3] = bias1[nt];
            }
#pragma unroll
            for (int ks = 0; ks < 2; ++ks) {
                uint32_t a[4];
                ldm_x4(axb_r + (uint32_t)(m0 * 16 * (KXP * 2) + ks * 32), a);
#pragma unroll
                for (int np = 0; np < 2; ++np) {
                    mma16816(acc0[2 * np],     a[0], a[1], a[2], a[3], bxf[ks][np][0], bxf[ks][np][1]);
                    mma16816(acc0[2 * np + 1], a[0], a[1], a[2], a[3], bxf[ks][np][2], bxf[ks][np][3]);
                }
                if (has1) {
                    uint32_t a1[4];
                    ldm_x4(axb_r + (uint32_t)((m0 + 1) * 16 * (KXP * 2) + ks * 32), a1);
#pragma unroll
                    for (int np = 0; np < 2; ++np) {
                        mma16816(acc1[2 * np],     a1[0], a1[1], a1[2], a1[3], bxf[ks][np][0], bxf[ks][np][1]);
                        mma16816(acc1[2 * np + 1], a1[0], a1[1], a1[2], a1[3], bxf[ks][np][2], bxf[ks][np][3]);
                    }
                }
            }
#pragma unroll
            for (int ks = 0; ks < 8; ++ks) {
                uint32_t b0[4], b1[4];
                ldm_x4(whb[0] + (((uint32_t)(ks * 32) + bko2) ^ xorv), b0);
                ldm_x4(whb[1] + (((uint32_t)(ks * 32) + bko2) ^ xorv), b1);
                uint32_t a[4];
                ldm_x4(ahb_r + (uint32_t)(m0 * 4096) + (((uint32_t)(ks * 32) + ako2) ^ xorv), a);
                mma16816(acc0[0], a[0], a[1], a[2], a[3], b0[0], b0[1]);
                mma16816(acc0[1], a[0], a[1], a[2], a[3], b0[2], b0[3]);
                mma16816(acc0[2], a[0], a[1], a[2], a[3], b1[0], b1[1]);
                mma16816(acc0[3], a[0], a[1], a[2], a[3], b1[2], b1[3]);
                if (has1) {
                    uint32_t a1[4];
                    ldm_x4(ahb_r + (uint32_t)((m0 + 1) * 4096) + (((uint32_t)(ks * 32) + ako2) ^ xorv), a1);
                    mma16816(acc1[0], a1[0], a1[1], a1[2], a1[3], b0[0], b0[1]);
                    mma16816(acc1[1], a1[0], a1[1], a1[2], a1[3], b0[2], b0[3]);
                    mma16816(acc1[2], a1[0], a1[1], a1[2], a1[3], b1[0], b1[1]);
                    mma16816(acc1[3], a1[0], a1[1], a1[2], a1[3], b1[2], b1[3]);
                }
            }

            epilogue(m0, acc0);
            if (has1) epilogue(m0 + 1, acc1);
        }
    }
}

// ---------------- CSR build ----------------------------------------------------
__global__ void csr_count_kernel(const int* __restrict__ ei) {
    int e = blockIdx.x * blockDim.x + threadIdx.x;
    if (e >= ETOT) return;
    int d = (e < EE) ? ei[EE + e] : (e - EE);
    atomicAdd(&g_cnt[d], 1);
}
__global__ __launch_bounds__(1024) void csr_scan_kernel() {
    __shared__ int swarp[32];
    const int t = threadIdx.x;
    const int lane = t & 31, wid = t >> 5;
    const int ITEMS = (NN + 1023) / 1024;
    const int base = t * ITEMS;

    int c[ITEMS];
    int total = 0;
#pragma unroll
    for (int i = 0; i < ITEMS; ++i) {
        int idx = base + i;
        c[i] = (idx < NN) ? g_cnt[idx] : 0;
        total += c[i];
        if (idx < NN) g_cnt[idx] = 0;
    }
    int incl = total;
#pragma unroll
    for (int o = 1; o < 32; o <<= 1) {
        int v = __shfl_up_sync(0xffffffffu, incl, o);
        if (lane >= o) incl += v;
    }
    if (lane == 31) swarp[wid] = incl;
    __syncthreads();
    if (wid == 0) {
        int w = swarp[lane];
        int wi = w;
#pragma unroll
        for (int o = 1; o < 32; o <<= 1) {
            int v = __shfl_up_sync(0xffffffffu, wi, o);
            if (lane >= o) wi += v;
        }
        swarp[lane] = wi - w;
    }
    __syncthreads();
    int run = swarp[wid] + (incl - total);
#pragma unroll
    for (int i = 0; i < ITEMS; ++i) {
        int idx = base + i;
        if (idx < NN) {
            g_row[idx] = run;
            g_cur[idx] = run;
            run += c[i];
        }
    }
    if (t == 1023) g_row[NN] = run;
}
__global__ void csr_scatter_kernel(const int* __restrict__ ei) {
    int e = blockIdx.x * blockDim.x + threadIdx.x;
    if (e >= ETOT) return;
    int s, d;
    if (e < EE) { s = ei[e]; d = ei[EE + e]; } else { s = e - EE; d = s; }
    int pos = atomicAdd(&g_cur[d], 1);
    g_csr[pos] = s;
}

// ---------------- fused GAT dense: xh = X@W (HMMA) + attn dots ----------------
__global__ __launch_bounds__(128) void gat_gemm_attn_kernel(
    const float* __restrict__ W, const float* __restrict__ a_src,
    const float* __restrict__ a_dst, int layer)
{
    const float* __restrict__ X = (layer == 0) ? g_h : g_feat;
    extern __shared__ char smem[];
    float* sas = (float*)(smem + GOFF_AS);
    float* sad = (float*)(smem + GOFF_AD);
    const uint32_t sA = (uint32_t)__cvta_generic_to_shared(smem + GOFF_A);
    const uint32_t sB = (uint32_t)__cvta_generic_to_shared(smem + GOFF_B);

    const int tid = threadIdx.x;
    const int n64 = blockIdx.x * 64;

    for (int i = tid; i < 64 * 128; i += 128) {
        int r = i >> 7, k = i & 127;
        float v = (n64 + r < NN) ? X[(n64 + r) * GGDIM + k] : 0.0f;
        uint32_t byte = (uint32_t)(r * 256 + (((k >> 3) ^ (r & 7)) << 4) + ((k & 7) << 1));
        *(__half*)(smem + GOFF_A + byte) = __float2half_rn(v);
    }
    for (int i = tid; i < 128 * 128; i += 128) {
        int n = i >> 7, k = i & 127;
        uint32_t byte = (uint32_t)(n * 256 + (((k >> 3) ^ (n & 7)) << 4) + ((k & 7) << 1));
        *(__half*)(smem + GOFF_B + byte) = __float2half_rn(W[k * GGDIM + n]);
    }
    if (tid < 128) { sas[tid] = a_src[tid]; sad[tid] = a_dst[tid]; }
    __syncthreads();

    const int wid  = tid >> 5;
    const int lane = tid & 31;
    const int g    = lane >> 2;
    const int cc   = lane & 3;
    const int sub = lane >> 3, rr = lane & 7;
    const int arow = (sub & 1) * 8 + rr;
    const int akof = (sub >> 1) * 8;
    const int bcol = rr + ((sub >> 1) * 8);
    const int bkof = (sub & 1) * 8;
    const uint32_t xorv = (uint32_t)(rr << 4);
    const uint32_t ako2 = (uint32_t)(akof << 1);
    const uint32_t bko2 = (uint32_t)(bkof << 1);
    const uint32_t arowb = sA + (uint32_t)(wid * 16 + arow) * 256;

    float acc[16][4];
#pragma unroll
    for (int q = 0; q < 16; ++q)
#pragma unroll
        for (int z = 0; z < 4; ++z) acc[q][z] = 0.0f;

#pragma unroll
    for (int ks = 0; ks < 8; ++ks) {
        uint32_t a[4];
        ldm_x4(arowb + (((uint32_t)(ks * 32) + ako2) ^ xorv), a);
#pragma unroll
        for (int np = 0; np < 8; ++np) {
            uint32_t b[4];
            ldm_x4(sB + (uint32_t)(np * 16 + bcol) * 256 + (((uint32_t)(ks * 32) + bko2) ^ xorv), b);
            mma16816(acc[2 * np],     a[0], a[1], a[2], a[3], b[0], b[1]);
            mma16816(acc[2 * np + 1], a[0], a[1], a[2], a[3], b[2], b[3]);
        }
    }

    const int gr0 = n64 + wid * 16 + g;
    const int gr1 = gr0 + 8;
#pragma unroll
    for (int np = 0; np < 8; ++np) {
        int c0 = np * 16 + 2 * cc, c1 = np * 16 + 8 + 2 * cc;
        if (gr0 < NN) {
            *(float2*)&g_xh[gr0 * GGDIM + c0] = make_float2(acc[2 * np][0], acc[2 * np][1]);
            *(float2*)&g_xh[gr0 * GGDIM + c1] = make_float2(acc[2 * np + 1][0], acc[2 * np + 1][1]);
        }
        if (gr1 < NN) {
            *(float2*)&g_xh[gr1 * GGDIM + c0] = make_float2(acc[2 * np][2], acc[2 * np][3]);
            *(float2*)&g_xh[gr1 * GGDIM + c1] = make_float2(acc[2 * np + 1][2], acc[2 * np + 1][3]);
        }
    }

    float rs0[4], rs1[4], rd0[4], rd1[4];
#pragma unroll
    for (int h = 0; h < 4; ++h) {
        float s0 = 0.0f, s1 = 0.0f, d0 = 0.0f, d1 = 0.0f;
#pragma unroll
        for (int tti = 0; tti < 4; ++tti) {
            int np = h * 2 + (tti >> 1);
            int ai = 2 * np + (tti & 1);
            int col = np * 16 + (tti & 1) * 8 + 2 * cc;
            float w0s = sas[col], w1s = sas[col + 1];
            float w0d = sad[col], w1d = sad[col + 1];
            s0 += acc[ai][0] * w0s + acc[ai][1] * w1s;
            s1 += acc[ai][2] * w0s + acc[ai][3] * w1s;
            d0 += acc[ai][0] * w0d + acc[ai][1] * w1d;
            d1 += acc[ai][2] * w0d + acc[ai][3] * w1d;
        }
        s0 += __shfl_xor_sync(0xffffffffu, s0, 1); s0 += __shfl_xor_sync(0xffffffffu, s0, 2);
        s1 += __shfl_xor_sync(0xffffffffu, s1, 1); s1 += __shfl_xor_sync(0xffffffffu, s1, 2);
        d0 += __shfl_xor_sync(0xffffffffu, d0, 1); d0 += __shfl_xor_sync(0xffffffffu, d0, 2);
        d1 += __shfl_xor_sync(0xffffffffu, d1, 1); d1 += __shfl_xor_sync(0xffffffffu, d1, 2);
        rs0[h] = s0; rs1[h] = s1; rd0[h] = d0; rd1[h] = d1;
    }
    if (gr0 < NN) { g_asr[gr0 * 4 + cc] = rs0[cc]; g_adt[gr0 * 4 + cc] = rd0[cc]; }
    if (gr1 < NN) { g_asr[gr1 * 4 + cc] = rs1[cc]; g_adt[gr1 * 4 + cc] = rd1[cc]; }
}

// -------- fused softmax + aggregate + bias + ELU (+ optional head) ------------
__global__ __launch_bounds__(256) void gat_agg_kernel(
    const float* __restrict__ bias, const float* __restrict__ Wh,
    const float* __restrict__ bh, float* __restrict__ out, int last)
{
    const int d    = (blockIdx.x * 256 + threadIdx.x) >> 5;
    const int lane = threadIdx.x & 31;
    if (d >= NN) return;
    const int start = g_row[d], end = g_row[d + 1];

    const float4 adt4 = *(const float4*)&g_adt[d * 4];

    float s0 = 0.0f, s1 = 0.0f, s2 = 0.0f, s3 = 0.0f;
    for (int idx = start + lane; idx < end; idx += 32) {
        int s = g_csr[idx];
        float4 a = *(const float4*)&g_asr[s * 4];
        s0 += __expf(lrelu(a.x + adt4.x));
        s1 += __expf(lrelu(a.y + adt4.y));
        s2 += __expf(lrelu(a.z + adt4.z));
        s3 += __expf(lrelu(a.w + adt4.w));
    }
#pragma unroll
    for (int off = 16; off > 0; off >>= 1) {
        s0 += __shfl_xor_sync(0xffffffffu, s0, off);
        s1 += __shfl_xor_sync(0xffffffffu, s1, off);
        s2 += __shfl_xor_sync(0xffffffffu, s2, off);
        s3 += __shfl_xor_sync(0xffffffffu, s3, off);
    }

    const int head = lane >> 3;
    float adt_h, den_h;
    if (head == 0)      { adt_h = adt4.x; den_h = s0; }
    else if (head == 1) { adt_h = adt4.y; den_h = s1; }
    else if (head == 2) { adt_h = adt4.z; den_h = s2; }
    else                { adt_h = adt4.w; den_h = s3; }
    const float inv_den = 1.0f / (den_h + 1e-16f);

    float4 acc = make_float4(0.0f, 0.0f, 0.0f, 0.0f);
    for (int idx = start; idx < end; ++idx) {
        int s = g_csr[idx];
        float as_h = g_asr[s * 4 + head];
        float alpha = __expf(lrelu(as_h + adt_h)) * inv_den;
        float4 xv = *(const float4*)&g_xh[s * GGDIM + lane * 4];
        acc.x = fmaf(alpha, xv.x, acc.x);
        acc.y = fmaf(alpha, xv.y, acc.y);
        acc.z = fmaf(alpha, xv.z, acc.z);
        acc.w = fmaf(alpha, xv.w, acc.w);
    }

    const float4 bv = *(const float4*)&bias[lane * 4];
    float4 outv;
    float v;
    v = acc.x + bv.x; outv.x = v > 0.0f ? v : (__expf(v) - 1.0f);
    v = acc.y + bv.y; outv.y = v > 0.0f ? v : (__expf(v) - 1.0f);
    v = acc.z + bv.z; outv.z = v > 0.0f ? v : (__expf(v) - 1.0f);
    v = acc.w + bv.w; outv.w = v > 0.0f ? v : (__expf(v) - 1.0f);

    if (!last) {
        *(float4*)&g_feat[d * GGDIM + lane * 4] = outv;
    } else {
        int ch = lane * 4;
        float p0 = outv.x * Wh[2 * ch + 0] + outv.y * Wh[2 * ch + 2]
                 + outv.z * Wh[2 * ch + 4] + outv.w * Wh[2 * ch + 6];
        float p1 = outv.x * Wh[2 * ch + 1] + outv.y * Wh[2 * ch + 3]
                 + outv.z * Wh[2 * ch + 5] + outv.w * Wh[2 * ch + 7];
#pragma unroll
        for (int off = 16; off > 0; off >>= 1) {
            p0 += __shfl_xor_sync(0xffffffffu, p0, off);
            p1 += __shfl_xor_sync(0xffffffffu, p1, off);
        }
        if (lane == 0) {
            out[2 * d + 0] = p0 + bh[0];
            out[2 * d + 1] = p1 + bh[1];
        }
    }
}

// ---------------- launch --------------------------------------------------------
extern "C" void kernel_launch(void* const* d_in, const int* in_sizes, int n_in,
                              void* d_out, int out_size) {
    const float* x_win  = (const float*)d_in[0];
    const int*   ei     = (const int*)  d_in[1];
    const float* Wih    = (const float*)d_in[2];
    const float* Whh    = (const float*)d_in[3];
    const float* bih    = (const float*)d_in[4];
    const float* bhh    = (const float*)d_in[5];
    const float* W1     = (const float*)d_in[6];
    const float* asrc1  = (const float*)d_in[7];
    const float* adst1  = (const float*)d_in[8];
    const float* b1     = (const float*)d_in[9];
    const float* W2     = (const float*)d_in[10];
    const float* asrc2  = (const float*)d_in[11];
    const float* adst2  = (const float*)d_in[12];
    const float* b2     = (const float*)d_in[13];
    const float* Wh     = (const float*)d_in[14];
    const float* bh     = (const float*)d_in[15];
    float* out = (float*)d_out;

    static cudaStream_t s_aux = nullptr;
    static cudaEvent_t  ev_fork = nullptr, ev_join = nullptr;
    static bool attr_done = false;
    if (!attr_done) {
        cudaFuncSetAttribute(lstm_all_kernel,
                             cudaFuncAttributeMaxDynamicSharedMemorySize, SMEM_TOTAL);
        cudaFuncSetAttribute(gat_gemm_attn_kernel,
                             cudaFuncAttributeMaxDynamicSharedMemorySize, GSMEM);
        cudaStreamCreateWithFlags(&s_aux, cudaStreamNonBlocking);
        cudaEventCreateWithFlags(&ev_fork, cudaEventDisableTiming);
        cudaEventCreateWithFlags(&ev_join, cudaEventDisableTiming);
        attr_done = true;
    }

    // fork: CSR build runs concurrently with the LSTM (independent inputs)
    cudaEventRecord(ev_fork, 0);
    cudaStreamWaitEvent(s_aux, ev_fork, 0);

    lstm_all_kernel<<<LGRID, LTHR, SMEM_TOTAL>>>(x_win, Wih, Whh, bih, bhh);

    csr_count_kernel<<<(ETOT + 255) / 256, 256, 0, s_aux>>>(ei);
    csr_scan_kernel<<<1, 1024, 0, s_aux>>>();
    csr_scatter_kernel<<<(ETOT + 255) / 256, 256, 0, s_aux>>>(ei);
    cudaEventRecord(ev_join, s_aux);
    cudaStreamWaitEvent(0, ev_join, 0);

    for (int layer = 0; layer < 2; layer++) {
        const float* W    = layer ? W2    : W1;
        const float* asrc = layer ? asrc2 : asrc1;
        const float* adst = layer ? adst2 : adst1;
        const float* bb   = layer ? b2    : b1;

        gat_gemm_attn_kernel<<<(NN + 63) / 64, 128, GSMEM>>>(W, asrc, adst, layer);
        gat_agg_kernel<<<(NN * 32 + 255) / 256, 256>>>(bb, Wh, bh, out, layer);
    }
}

// round 16
// speedup vs baseline: 1.2274x; 1.0066x over previous
#include <cuda_runtime.h>
#include <cuda_fp16.h>
#include <math.h>
#include <stdint.h>

// ---------------- problem constants ------------------------------------------
#define NN      20000
#define TT      60
#define DDIM    20
#define HH      128
#define GGDIM   128
#define NHEADS  4
#define CCH     32
#define EE      320000
#define ETOT    (EE + NN)
#define G4      512
#define LNODES  144
#define MTILES  9
#define LGRID   139
#define GSTR    (LGRID * LNODES)
#define LTHR    512

#define KXP     40                  // AX row stride in halves (80B, conflict-free)
#define AXE     (LNODES * DDIM)

// ---------------- LSTM smem layout (bytes) -----------------------------------
#define OFF_WH   0                          // 512 x 256B swizzled   (131072)
#define OFF_AH0  131072                     // 144 x 256B swizzled   (36864)
#define OFF_AH1  167936                     // 144 x 256B swizzled   (36864)
#define OFF_WX   167936                     // init-only overlay     (40960)
#define OFF_AX0  204800                     // 144 x 40 f16          (11520)
#define OFF_AX1  216320                     // 144 x 40 f16          (11520)
#define OFF_BIAS 227840                     // 512 f32               (2048)
#define SMEM_TOTAL 229888

// ---------------- GAT gemm+attn smem layout (bytes, dynamic) ------------------
#define GOFF_A   0
#define GOFF_B   16384
#define GOFF_AS  49152
#define GOFF_AD  49664
#define GSMEM    50176

// ---------------- scratch (device globals) ------------------------------------
__device__ float g_h[GSTR * HH];
__device__ float g_xh[NN * GGDIM];
__device__ float g_feat[NN * GGDIM];
__device__ float g_asr[NN * NHEADS];
__device__ float g_adt[NN * NHEADS];
__device__ int   g_cnt[NN];          // loader-zeroed; re-zeroed by scan each call
__device__ int   g_row[NN + 1];
__device__ int   g_cur[NN];
__device__ int   g_csr[ETOT];

// ---------------- helpers -----------------------------------------------------
__device__ __forceinline__ float tanhapx(float x) {
    float y; asm("tanh.approx.f32 %0, %1;" : "=f"(y) : "f"(x)); return y;
}
__device__ __forceinline__ float sigt(float x) {
    return fmaf(tanhapx(0.5f * x), 0.5f, 0.5f);
}
__device__ __forceinline__ void mma16816(float* d,
                                         uint32_t a0, uint32_t a1, uint32_t a2, uint32_t a3,
                                         uint32_t b0, uint32_t b1) {
    asm volatile(
        "mma.sync.aligned.m16n8k16.row.col.f32.f16.f16.f32 "
        "{%0,%1,%2,%3}, {%4,%5,%6,%7}, {%8,%9}, {%0,%1,%2,%3};"
        : "+f"(d[0]), "+f"(d[1]), "+f"(d[2]), "+f"(d[3])
        : "r"(a0), "r"(a1), "r"(a2), "r"(a3), "r"(b0), "r"(b1));
}
__device__ __forceinline__ void ldm_x4(uint32_t addr, uint32_t* r) {
    asm volatile("ldmatrix.sync.aligned.m8n8.x4.shared.b16 {%0,%1,%2,%3}, [%4];"
                 : "=r"(r[0]), "=r"(r[1]), "=r"(r[2]), "=r"(r[3]) : "r"(addr));
}
__device__ __forceinline__ float lrelu(float v) { return v > 0.0f ? v : 0.2f * v; }

// gate-column permutation: n' = warp*32 + gate*8 + jloc
__device__ __forceinline__ int perm_row(int n) {
    return ((n >> 3) & 3) * HH + ((n >> 5) * 8 + (n & 7));
}

// ---------------- persistent LSTM kernel (unchanged from R14) -----------------
__global__ __launch_bounds__(LTHR, 1) void lstm_all_kernel(
    const float* __restrict__ x,
    const float* __restrict__ Wih, const float* __restrict__ Whh,
    const float* __restrict__ bih, const float* __restrict__ bhh)
{
    extern __shared__ char smem[];
    __half* WX = (__half*)(smem + OFF_WX);
    float*  sbias = (float*)(smem + OFF_BIAS);
    const uint32_t sWX  = (uint32_t)__cvta_generic_to_shared(smem + OFF_WX);
    const uint32_t sWH  = (uint32_t)__cvta_generic_to_shared(smem + OFF_WH);
    const uint32_t sAX0 = (uint32_t)__cvta_generic_to_shared(smem + OFF_AX0);
    const uint32_t sAX1 = (uint32_t)__cvta_generic_to_shared(smem + OFF_AX1);
    const uint32_t sAH0 = (uint32_t)__cvta_generic_to_shared(smem + OFF_AH0);
    const uint32_t sAH1 = (uint32_t)__cvta_generic_to_shared(smem + OFF_AH1);

    const int tid = threadIdx.x;
    const int blk = blockIdx.x;

    for (int i = tid; i < SMEM_TOTAL / 4; i += LTHR) ((uint32_t*)smem)[i] = 0;
    __syncthreads();

    for (int i = tid; i < G4 * DDIM; i += LTHR) {
        int n = i / DDIM, k = i - n * DDIM;
        int row = perm_row(n);
        WX[n * KXP + k] = __float2half_rn(Wih[row * DDIM + k]);
    }
    for (int i = tid; i < G4 * HH; i += LTHR) {
        int n = i >> 7, k = i & 127;
        int row = perm_row(n);
        uint32_t byte = (uint32_t)(n * 256 + ((((k >> 3) ^ (n & 7)) << 4)) + ((k & 7) << 1));
        *(__half*)(smem + OFF_WH + byte) = __float2half_rn(Whh[row * HH + k]);
    }
    for (int i = tid; i < G4; i += LTHR) {
        int row = perm_row(i);
        sbias[i] = bih[row] + bhh[row];
    }
    __syncthreads();

    const int wid  = tid >> 5;
    const int lane = tid & 31;
    const int g    = lane >> 2;
    const int cc   = lane & 3;
    const int n0   = wid * 32;
    const int j0   = (wid << 3) + 2 * cc;

    const int sub = lane >> 3, rr = lane & 7;
    const int arow = (sub & 1) * 8 + rr;
    const int akof = (sub >> 1) * 8;
    const int bcol = rr + ((sub >> 1) * 8);
    const int bkof = (sub & 1) * 8;
    const uint32_t axb0 = sAX0 + (uint32_t)(arow * KXP + akof) * 2;
    const uint32_t axb1 = sAX1 + (uint32_t)(arow * KXP + akof) * 2;
    const uint32_t ahbase0 = sAH0 + (uint32_t)arow * 256;
    const uint32_t ahbase1 = sAH1 + (uint32_t)arow * 256;
    const uint32_t xorv = (uint32_t)(rr << 4);
    const uint32_t ako2 = (uint32_t)(akof << 1);
    const uint32_t bko2 = (uint32_t)(bkof << 1);
    const uint32_t ahw_off = (uint32_t)(((wid ^ g) << 4) + 4 * cc);
    uint32_t wxb[2], whb[2];
#pragma unroll
    for (int np = 0; np < 2; ++np) {
        wxb[np] = sWX + (uint32_t)((n0 + np * 16 + bcol) * KXP + bkof) * 2;
        whb[np] = sWH + (uint32_t)(n0 + np * 16 + bcol) * 256;
    }

    float bias0[4], bias1[4];
#pragma unroll
    for (int nt = 0; nt < 4; ++nt) {
        bias0[nt] = sbias[n0 + nt * 8 + 2 * cc];
        bias1[nt] = sbias[n0 + nt * 8 + 2 * cc + 1];
    }

    uint32_t bxf[2][2][4];
#pragma unroll
    for (int ks = 0; ks < 2; ++ks)
#pragma unroll
        for (int np = 0; np < 2; ++np)
            ldm_x4(wxb[np] + (uint32_t)(ks * 32), bxf[ks][np]);

    float creg[MTILES][4];
#pragma unroll
    for (int mt = 0; mt < MTILES; ++mt)
#pragma unroll
        for (int nt = 0; nt < 4; ++nt) creg[mt][nt] = 0.0f;

    __syncthreads();

    {
        __half* AX = (__half*)(smem + OFF_AX0);
        for (int i = tid; i < AXE; i += LTHR) {
            int mm = i / DDIM, k = i - mm * DDIM;
            int n = blk * LNODES + mm;
            AX[mm * KXP + k] = __float2half_rn(n < NN ? x[n * (TT * DDIM) + 0 * DDIM + k] : 0.0f);
        }
    }

    for (int s = 0; s < TT; ++s) {
        __syncthreads();

        if (s + 1 < TT) {
            __half* AXN = (__half*)(smem + (((s + 1) & 1) ? OFF_AX1 : OFF_AX0));
            for (int i = tid; i < AXE; i += LTHR) {
                int mm = i / DDIM, k = i - mm * DDIM;
                int n = blk * LNODES + mm;
                AXN[mm * KXP + k] = __float2half_rn(n < NN ? x[n * (TT * DDIM) + (s + 1) * DDIM + k] : 0.0f);
            }
        }

        const bool last = (s == TT - 1);
        const uint32_t axb_r = (s & 1) ? axb1 : axb0;
        const uint32_t ahb_r = (s & 1) ? ahbase1 : ahbase0;
        char* AHWc = smem + ((s & 1) ? OFF_AH0 : OFF_AH1);

        auto epilogue = [&](int mt, float (&acc)[4][4]) {
#pragma unroll
            for (int hf = 0; hf < 2; ++hf) {
                const int row = mt * 16 + g + hf * 8;
                float hv[2];
#pragma unroll
                for (int b = 0; b < 2; ++b) {
                    const int z = hf * 2 + b;
                    float gi = acc[0][z], gf = acc[1][z];
                    float gg = acc[2][z], go = acc[3][z];
                    float cold = creg[mt][z];
                    float cn = sigt(gf) * cold + sigt(gi) * tanhapx(gg);
                    creg[mt][z] = cn;
                    hv[b] = sigt(go) * tanhapx(cn);
                }
                *(__half2*)(AHWc + (uint32_t)row * 256 + ahw_off) = __floats2half2_rn(hv[0], hv[1]);
                if (last)
                    *(float2*)&g_h[(blk * LNODES + row) * HH + j0] = make_float2(hv[0], hv[1]);
            }
        };

#pragma unroll
        for (int p = 0; p < 5; ++p) {
            const int m0 = 2 * p;
            const bool has1 = (m0 + 1 < MTILES);

            float acc0[4][4], acc1[4][4];
#pragma unroll
            for (int nt = 0; nt < 4; ++nt) {
                acc0[nt][0] = bias0[nt]; acc0[nt][1] = bias1[nt];
                acc0[nt][2] = bias0[nt]; acc0[nt][3] = bias1[nt];
                acc1[nt][0] = bias0[nt]; acc1[nt][1] = bias1[nt];
                acc1[nt][2] = bias0[nt]; acc1[nt][3] = bias1[nt];
            }
#pragma unroll
            for (int ks = 0; ks < 2; ++ks) {
                uint32_t a[4];
                ldm_x4(axb_r + (uint32_t)(m0 * 16 * (KXP * 2) + ks * 32), a);
#pragma unroll
                for (int np = 0; np < 2; ++np) {
                    mma16816(acc0[2 * np],     a[0], a[1], a[2], a[3], bxf[ks][np][0], bxf[ks][np][1]);
                    mma16816(acc0[2 * np + 1], a[0], a[1], a[2], a[3], bxf[ks][np][2], bxf[ks][np][3]);
                }
                if (has1) {
                    uint32_t a1[4];
                    ldm_x4(axb_r + (uint32_t)((m0 + 1) * 16 * (KXP * 2) + ks * 32), a1);
#pragma unroll
                    for (int np = 0; np < 2; ++np) {
                        mma16816(acc1[2 * np],     a1[0], a1[1], a1[2], a1[3], bxf[ks][np][0], bxf[ks][np][1]);
                        mma16816(acc1[2 * np + 1], a1[0], a1[1], a1[2], a1[3], bxf[ks][np][2], bxf[ks][np][3]);
                    }
                }
            }
#pragma unroll
            for (int ks = 0; ks < 8; ++ks) {
                uint32_t b0[4], b1[4];
                ldm_x4(whb[0] + (((uint32_t)(ks * 32) + bko2) ^ xorv), b0);
                ldm_x4(whb[1] + (((uint32_t)(ks * 32) + bko2) ^ xorv), b1);
                uint32_t a[4];
                ldm_x4(ahb_r + (uint32_t)(m0 * 4096) + (((uint32_t)(ks * 32) + ako2) ^ xorv), a);
                mma16816(acc0[0], a[0], a[1], a[2], a[3], b0[0], b0[1]);
                mma16816(acc0[1], a[0], a[1], a[2], a[3], b0[2], b0[3]);
                mma16816(acc0[2], a[0], a[1], a[2], a[3], b1[0], b1[1]);
                mma16816(acc0[3], a[0], a[1], a[2], a[3], b1[2], b1[3]);
                if (has1) {
                    uint32_t a1[4];
                    ldm_x4(ahb_r + (uint32_t)((m0 + 1) * 4096) + (((uint32_t)(ks * 32) + ako2) ^ xorv), a1);
                    mma16816(acc1[0], a1[0], a1[1], a1[2], a1[3], b0[0], b0[1]);
                    mma16816(acc1[1], a1[0], a1[1], a1[2], a1[3], b0[2], b0[3]);
                    mma16816(acc1[2], a1[0], a1[1], a1[2], a1[3], b1[0], b1[1]);
                    mma16816(acc1[3], a1[0], a1[1], a1[2], a1[3], b1[2], b1[3]);
                }
            }

            epilogue(m0, acc0);
            if (has1) epilogue(m0 + 1, acc1);
        }
    }
}

// ---------------- CSR build ----------------------------------------------------
__global__ void csr_count_kernel(const int* __restrict__ ei) {
    int e = blockIdx.x * blockDim.x + threadIdx.x;
    if (e >= ETOT) return;
    int d = (e < EE) ? ei[EE + e] : (e - EE);
    atomicAdd(&g_cnt[d], 1);
}
__global__ __launch_bounds__(1024) void csr_scan_kernel() {
    __shared__ int swarp[32];
    const int t = threadIdx.x;
    const int lane = t & 31, wid = t >> 5;
    const int ITEMS = (NN + 1023) / 1024;
    const int base = t * ITEMS;

    int c[ITEMS];
    int total = 0;
#pragma unroll
    for (int i = 0; i < ITEMS; ++i) {
        int idx = base + i;
        c[i] = (idx < NN) ? g_cnt[idx] : 0;
        total += c[i];
        if (idx < NN) g_cnt[idx] = 0;
    }
    int incl = total;
#pragma unroll
    for (int o = 1; o < 32; o <<= 1) {
        int v = __shfl_up_sync(0xffffffffu, incl, o);
        if (lane >= o) incl += v;
    }
    if (lane == 31) swarp[wid] = incl;
    __syncthreads();
    if (wid == 0) {
        int w = swarp[lane];
        int wi = w;
#pragma unroll
        for (int o = 1; o < 32; o <<= 1) {
            int v = __shfl_up_sync(0xffffffffu, wi, o);
            if (lane >= o) wi += v;
        }
        swarp[lane] = wi - w;
    }
    __syncthreads();
    int run = swarp[wid] + (incl - total);
#pragma unroll
    for (int i = 0; i < ITEMS; ++i) {
        int idx = base + i;
        if (idx < NN) {
            g_row[idx] = run;
            g_cur[idx] = run;
            run += c[i];
        }
    }
    if (t == 1023) g_row[NN] = run;
}
__global__ void csr_scatter_kernel(const int* __restrict__ ei) {
    int e = blockIdx.x * blockDim.x + threadIdx.x;
    if (e >= ETOT) return;
    int s, d;
    if (e < EE) { s = ei[e]; d = ei[EE + e]; } else { s = e - EE; d = s; }
    int pos = atomicAdd(&g_cur[d], 1);
    g_csr[pos] = s;
}

// ---------------- fused GAT dense: xh = X@W (HMMA) + attn dots ----------------
__global__ __launch_bounds__(128) void gat_gemm_attn_kernel(
    const float* __restrict__ W, const float* __restrict__ a_src,
    const float* __restrict__ a_dst, int layer)
{
    const float* __restrict__ X = (layer == 0) ? g_h : g_feat;
    extern __shared__ char smem[];
    float* sas = (float*)(smem + GOFF_AS);
    float* sad = (float*)(smem + GOFF_AD);
    const uint32_t sA = (uint32_t)__cvta_generic_to_shared(smem + GOFF_A);
    const uint32_t sB = (uint32_t)__cvta_generic_to_shared(smem + GOFF_B);

    const int tid = threadIdx.x;
    const int n64 = blockIdx.x * 64;

    for (int i = tid; i < 64 * 128; i += 128) {
        int r = i >> 7, k = i & 127;
        float v = (n64 + r < NN) ? X[(n64 + r) * GGDIM + k] : 0.0f;
        uint32_t byte = (uint32_t)(r * 256 + (((k >> 3) ^ (r & 7)) << 4) + ((k & 7) << 1));
        *(__half*)(smem + GOFF_A + byte) = __float2half_rn(v);
    }
    for (int i = tid; i < 128 * 128; i += 128) {
        int n = i >> 7, k = i & 127;
        uint32_t byte = (uint32_t)(n * 256 + (((k >> 3) ^ (n & 7)) << 4) + ((k & 7) << 1));
        *(__half*)(smem + GOFF_B + byte) = __float2half_rn(W[k * GGDIM + n]);
    }
    if (tid < 128) { sas[tid] = a_src[tid]; sad[tid] = a_dst[tid]; }
    __syncthreads();

    const int wid  = tid >> 5;
    const int lane = tid & 31;
    const int g    = lane >> 2;
    const int cc   = lane & 3;
    const int sub = lane >> 3, rr = lane & 7;
    const int arow = (sub & 1) * 8 + rr;
    const int akof = (sub >> 1) * 8;
    const int bcol = rr + ((sub >> 1) * 8);
    const int bkof = (sub & 1) * 8;
    const uint32_t xorv = (uint32_t)(rr << 4);
    const uint32_t ako2 = (uint32_t)(akof << 1);
    const uint32_t bko2 = (uint32_t)(bkof << 1);
    const uint32_t arowb = sA + (uint32_t)(wid * 16 + arow) * 256;

    float acc[16][4];
#pragma unroll
    for (int q = 0; q < 16; ++q)
#pragma unroll
        for (int z = 0; z < 4; ++z) acc[q][z] = 0.0f;

#pragma unroll
    for (int ks = 0; ks < 8; ++ks) {
        uint32_t a[4];
        ldm_x4(arowb + (((uint32_t)(ks * 32) + ako2) ^ xorv), a);
#pragma unroll
        for (int np = 0; np < 8; ++np) {
            uint32_t b[4];
            ldm_x4(sB + (uint32_t)(np * 16 + bcol) * 256 + (((uint32_t)(ks * 32) + bko2) ^ xorv), b);
            mma16816(acc[2 * np],     a[0], a[1], a[2], a[3], b[0], b[1]);
            mma16816(acc[2 * np + 1], a[0], a[1], a[2], a[3], b[2], b[3]);
        }
    }

    const int gr0 = n64 + wid * 16 + g;
    const int gr1 = gr0 + 8;
#pragma unroll
    for (int np = 0; np < 8; ++np) {
        int c0 = np * 16 + 2 * cc, c1 = np * 16 + 8 + 2 * cc;
        if (gr0 < NN) {
            *(float2*)&g_xh[gr0 * GGDIM + c0] = make_float2(acc[2 * np][0], acc[2 * np][1]);
            *(float2*)&g_xh[gr0 * GGDIM + c1] = make_float2(acc[2 * np + 1][0], acc[2 * np + 1][1]);
        }
        if (gr1 < NN) {
            *(float2*)&g_xh[gr1 * GGDIM + c0] = make_float2(acc[2 * np][2], acc[2 * np][3]);
            *(float2*)&g_xh[gr1 * GGDIM + c1] = make_float2(acc[2 * np + 1][2], acc[2 * np + 1][3]);
        }
    }

    float rs0[4], rs1[4], rd0[4], rd1[4];
#pragma unroll
    for (int h = 0; h < 4; ++h) {
        float s0 = 0.0f, s1 = 0.0f, d0 = 0.0f, d1 = 0.0f;
#pragma unroll
        for (int tti = 0; tti < 4; ++tti) {
            int np = h * 2 + (tti >> 1);
            int ai = 2 * np + (tti & 1);
            int col = np * 16 + (tti & 1) * 8 + 2 * cc;
            float w0s = sas[col], w1s = sas[col + 1];
            float w0d = sad[col], w1d = sad[col + 1];
            s0 += acc[ai][0] * w0s + acc[ai][1] * w1s;
            s1 += acc[ai][2] * w0s + acc[ai][3] * w1s;
            d0 += acc[ai][0] * w0d + acc[ai][1] * w1d;
            d1 += acc[ai][2] * w0d + acc[ai][3] * w1d;
        }
        s0 += __shfl_xor_sync(0xffffffffu, s0, 1); s0 += __shfl_xor_sync(0xffffffffu, s0, 2);
        s1 += __shfl_xor_sync(0xffffffffu, s1, 1); s1 += __shfl_xor_sync(0xffffffffu, s1, 2);
        d0 += __shfl_xor_sync(0xffffffffu, d0, 1); d0 += __shfl_xor_sync(0xffffffffu, d0, 2);
        d1 += __shfl_xor_sync(0xffffffffu, d1, 1); d1 += __shfl_xor_sync(0xffffffffu, d1, 2);
        rs0[h] = s0; rs1[h] = s1; rd0[h] = d0; rd1[h] = d1;
    }
    if (gr0 < NN) { g_asr[gr0 * 4 + cc] = rs0[cc]; g_adt[gr0 * 4 + cc] = rd0[cc]; }
    if (gr1 < NN) { g_asr[gr1 * 4 + cc] = rs1[cc]; g_adt[gr1 * 4 + cc] = rd1[cc]; }
}

// -------- single-pass softmax-aggregate + bias + ELU (+ optional head) --------
// out_d = (Σ_e exp(e)·xh_src) / (Σ_e exp(e)) — unnormalized accumulation,
// one divide at the end; no warp reductions, one edge sweep instead of two.
__global__ __launch_bounds__(256) void gat_agg_kernel(
    const float* __restrict__ bias, const float* __restrict__ Wh,
    const float* __restrict__ bh, float* __restrict__ out, int last)
{
    const int d    = (blockIdx.x * 256 + threadIdx.x) >> 5;
    const int lane = threadIdx.x & 31;
    if (d >= NN) return;
    const int start = g_row[d], end = g_row[d + 1];

    const int head = lane >> 3;
    const float adt_h = g_adt[d * 4 + head];

    float den = 0.0f;
    float4 acc = make_float4(0.0f, 0.0f, 0.0f, 0.0f);
#pragma unroll 4
    for (int idx = start; idx < end; ++idx) {
        int s = g_csr[idx];                                  // warp-uniform
        float e = __expf(lrelu(g_asr[s * 4 + head] + adt_h));
        float4 xv = *(const float4*)&g_xh[s * GGDIM + lane * 4];
        den += e;
        acc.x = fmaf(e, xv.x, acc.x);
        acc.y = fmaf(e, xv.y, acc.y);
        acc.z = fmaf(e, xv.z, acc.z);
        acc.w = fmaf(e, xv.w, acc.w);
    }
    const float inv_den = 1.0f / (den + 1e-16f);

    const float4 bv = *(const float4*)&bias[lane * 4];
    float4 outv;
    float v;
    v = fmaf(acc.x, inv_den, bv.x); outv.x = v > 0.0f ? v : (__expf(v) - 1.0f);
    v = fmaf(acc.y, inv_den, bv.y); outv.y = v > 0.0f ? v : (__expf(v) - 1.0f);
    v = fmaf(acc.z, inv_den, bv.z); outv.z = v > 0.0f ? v : (__expf(v) - 1.0f);
    v = fmaf(acc.w, inv_den, bv.w); outv.w = v > 0.0f ? v : (__expf(v) - 1.0f);

    if (!last) {
        *(float4*)&g_feat[d * GGDIM + lane * 4] = outv;
    } else {
        int ch = lane * 4;
        float p0 = outv.x * Wh[2 * ch + 0] + outv.y * Wh[2 * ch + 2]
                 + outv.z * Wh[2 * ch + 4] + outv.w * Wh[2 * ch + 6];
        float p1 = outv.x * Wh[2 * ch + 1] + outv.y * Wh[2 * ch + 3]
                 + outv.z * Wh[2 * ch + 5] + outv.w * Wh[2 * ch + 7];
#pragma unroll
        for (int off = 16; off > 0; off >>= 1) {
            p0 += __shfl_xor_sync(0xffffffffu, p0, off);
            p1 += __shfl_xor_sync(0xffffffffu, p1, off);
        }
        if (lane == 0) {
            out[2 * d + 0] = p0 + bh[0];
            out[2 * d + 1] = p1 + bh[1];
        }
    }
}

// ---------------- launch --------------------------------------------------------
extern "C" void kernel_launch(void* const* d_in, const int* in_sizes, int n_in,
                              void* d_out, int out_size) {
    const float* x_win  = (const float*)d_in[0];
    const int*   ei     = (const int*)  d_in[1];
    const float* Wih    = (const float*)d_in[2];
    const float* Whh    = (const float*)d_in[3];
    const float* bih    = (const float*)d_in[4];
    const float* bhh    = (const float*)d_in[5];
    const float* W1     = (const float*)d_in[6];
    const float* asrc1  = (const float*)d_in[7];
    const float* adst1  = (const float*)d_in[8];
    const float* b1     = (const float*)d_in[9];
    const float* W2     = (const float*)d_in[10];
    const float* asrc2  = (const float*)d_in[11];
    const float* adst2  = (const float*)d_in[12];
    const float* b2     = (const float*)d_in[13];
    const float* Wh     = (const float*)d_in[14];
    const float* bh     = (const float*)d_in[15];
    float* out = (float*)d_out;

    static cudaStream_t s_aux = nullptr;
    static cudaEvent_t  ev_fork = nullptr, ev_join = nullptr;
    static bool attr_done = false;
    if (!attr_done) {
        cudaFuncSetAttribute(lstm_all_kernel,
                             cudaFuncAttributeMaxDynamicSharedMemorySize, SMEM_TOTAL);
        cudaFuncSetAttribute(gat_gemm_attn_kernel,
                             cudaFuncAttributeMaxDynamicSharedMemorySize, GSMEM);
        cudaStreamCreateWithFlags(&s_aux, cudaStreamNonBlocking);
        cudaEventCreateWithFlags(&ev_fork, cudaEventDisableTiming);
        cudaEventCreateWithFlags(&ev_join, cudaEventDisableTiming);
        attr_done = true;
    }

    // fork: CSR build runs concurrently with the LSTM (independent inputs)
    cudaEventRecord(ev_fork, 0);
    cudaStreamWaitEvent(s_aux, ev_fork, 0);

    lstm_all_kernel<<<LGRID, LTHR, SMEM_TOTAL>>>(x_win, Wih, Whh, bih, bhh);

    csr_count_kernel<<<(ETOT + 255) / 256, 256, 0, s_aux>>>(ei);
    csr_scan_kernel<<<1, 1024, 0, s_aux>>>();
    csr_scatter_kernel<<<(ETOT + 255) / 256, 256, 0, s_aux>>>(ei);
    cudaEventRecord(ev_join, s_aux);
    cudaStreamWaitEvent(0, ev_join, 0);

    for (int layer = 0; layer < 2; layer++) {
        const float* W    = layer ? W2    : W1;
        const float* asrc = layer ? asrc2 : asrc1;
        const float* adst = layer ? adst2 : adst1;
        const float* bb   = layer ? b2    : b1;

        gat_gemm_attn_kernel<<<(NN + 63) / 64, 128, GSMEM>>>(W, asrc, adst, layer);
        gat_agg_kernel<<<(NN * 32 + 255) / 256, 256>>>(bb, Wh, bh, out, layer);
    }
}

// round 17
// speedup vs baseline: 1.2918x; 1.0524x over previous
#include <cuda_runtime.h>
#include <cuda_fp16.h>
#include <math.h>
#include <stdint.h>

// ---------------- problem constants ------------------------------------------
#define NN      20000
#define TT      60
#define DDIM    20
#define HH      128
#define GGDIM   128
#define NHEADS  4
#define CCH     32
#define EE      320000
#define ETOT    (EE + NN)
#define G4      512
#define LNODES  144
#define MTILES  9
#define LGRID   139
#define GSTR    (LGRID * LNODES)
#define LTHR    512
#define NT64    313                 // ceil(NN/64) GAT tiles

#define KXP     40
#define AXE     (LNODES * DDIM)

// ---------------- LSTM smem layout (bytes) -----------------------------------
#define OFF_WH   0                          // 512 x 256B swizzled   (131072)
#define OFF_AH0  131072                     // 144 x 256B swizzled   (36864)
#define OFF_AH1  167936                     // 144 x 256B swizzled   (36864)
#define OFF_WX   167936                     // init-only overlay     (40960)
#define OFF_AX0  204800                     // 144 x 40 f16          (11520)
#define OFF_AX1  216320                     // 144 x 40 f16          (11520)
#define OFF_BIAS 227840                     // 512 f32               (2048)
#define SMEM_TOTAL 229888

// ---------------- GAT gemm+attn smem layout (bytes, dynamic) ------------------
#define GOFF_A   0
#define GOFF_B   16384
#define GOFF_AS  49152
#define GOFF_AD  49664
#define GSMEM    50176

// ---------------- scratch (device globals; uint4 for 16B alignment) -----------
__device__ uint4 g_hh[NT64 * 1024];     // h, fp16, 64-row tiles, swizzled 256B rows
__device__ uint4 g_ft16[NT64 * 1024];   // feat, fp16, same layout
__device__ uint4 g_xh16[NN * 16];       // xh, fp16, row-major 256B rows
__device__ uint4 g_w16[2][2048];        // W1/W2, fp16, swizzled (col-frag rows)
__device__ float g_asr[NN * NHEADS];
__device__ float g_adt[NN * NHEADS];
__device__ int   g_cnt[NN];
__device__ int   g_row[NN + 1];
__device__ int   g_cur[NN];
__device__ int   g_csr[ETOT];

// ---------------- helpers -----------------------------------------------------
__device__ __forceinline__ float tanhapx(float x) {
    float y; asm("tanh.approx.f32 %0, %1;" : "=f"(y) : "f"(x)); return y;
}
__device__ __forceinline__ float sigt(float x) {
    return fmaf(tanhapx(0.5f * x), 0.5f, 0.5f);
}
__device__ __forceinline__ void mma16816(float* d,
                                         uint32_t a0, uint32_t a1, uint32_t a2, uint32_t a3,
                                         uint32_t b0, uint32_t b1) {
    asm volatile(
        "mma.sync.aligned.m16n8k16.row.col.f32.f16.f16.f32 "
        "{%0,%1,%2,%3}, {%4,%5,%6,%7}, {%8,%9}, {%0,%1,%2,%3};"
        : "+f"(d[0]), "+f"(d[1]), "+f"(d[2]), "+f"(d[3])
        : "r"(a0), "r"(a1), "r"(a2), "r"(a3), "r"(b0), "r"(b1));
}
__device__ __forceinline__ void ldm_x4(uint32_t addr, uint32_t* r) {
    asm volatile("ldmatrix.sync.aligned.m8n8.x4.shared.b16 {%0,%1,%2,%3}, [%4];"
                 : "=r"(r[0]), "=r"(r[1]), "=r"(r[2]), "=r"(r[3]) : "r"(addr));
}
__device__ __forceinline__ float lrelu(float v) { return v > 0.0f ? v : 0.2f * v; }

// gate-column permutation: n' = warp*32 + gate*8 + jloc
__device__ __forceinline__ int perm_row(int n) {
    return ((n >> 3) & 3) * HH + ((n >> 5) * 8 + (n & 7));
}

// ---------------- persistent LSTM kernel --------------------------------------
__global__ __launch_bounds__(LTHR, 1) void lstm_all_kernel(
    const float* __restrict__ x,
    const float* __restrict__ Wih, const float* __restrict__ Whh,
    const float* __restrict__ bih, const float* __restrict__ bhh)
{
    extern __shared__ char smem[];
    __half* WX = (__half*)(smem + OFF_WX);
    float*  sbias = (float*)(smem + OFF_BIAS);
    const uint32_t sWX  = (uint32_t)__cvta_generic_to_shared(smem + OFF_WX);
    const uint32_t sWH  = (uint32_t)__cvta_generic_to_shared(smem + OFF_WH);
    const uint32_t sAX0 = (uint32_t)__cvta_generic_to_shared(smem + OFF_AX0);
    const uint32_t sAX1 = (uint32_t)__cvta_generic_to_shared(smem + OFF_AX1);
    const uint32_t sAH0 = (uint32_t)__cvta_generic_to_shared(smem + OFF_AH0);
    const uint32_t sAH1 = (uint32_t)__cvta_generic_to_shared(smem + OFF_AH1);

    const int tid = threadIdx.x;
    const int blk = blockIdx.x;

    for (int i = tid; i < SMEM_TOTAL / 4; i += LTHR) ((uint32_t*)smem)[i] = 0;
    __syncthreads();

    for (int i = tid; i < G4 * DDIM; i += LTHR) {
        int n = i / DDIM, k = i - n * DDIM;
        int row = perm_row(n);
        WX[n * KXP + k] = __float2half_rn(Wih[row * DDIM + k]);
    }
    for (int i = tid; i < G4 * HH; i += LTHR) {
        int n = i >> 7, k = i & 127;
        int row = perm_row(n);
        uint32_t byte = (uint32_t)(n * 256 + ((((k >> 3) ^ (n & 7)) << 4)) + ((k & 7) << 1));
        *(__half*)(smem + OFF_WH + byte) = __float2half_rn(Whh[row * HH + k]);
    }
    for (int i = tid; i < G4; i += LTHR) {
        int row = perm_row(i);
        sbias[i] = bih[row] + bhh[row];
    }
    __syncthreads();

    const int wid  = tid >> 5;
    const int lane = tid & 31;
    const int g    = lane >> 2;
    const int cc   = lane & 3;
    const int n0   = wid * 32;
    const int j0   = (wid << 3) + 2 * cc;

    const int sub = lane >> 3, rr = lane & 7;
    const int arow = (sub & 1) * 8 + rr;
    const int akof = (sub >> 1) * 8;
    const int bcol = rr + ((sub >> 1) * 8);
    const int bkof = (sub & 1) * 8;
    const uint32_t axb0 = sAX0 + (uint32_t)(arow * KXP + akof) * 2;
    const uint32_t axb1 = sAX1 + (uint32_t)(arow * KXP + akof) * 2;
    const uint32_t ahbase0 = sAH0 + (uint32_t)arow * 256;
    const uint32_t ahbase1 = sAH1 + (uint32_t)arow * 256;
    const uint32_t xorv = (uint32_t)(rr << 4);
    const uint32_t ako2 = (uint32_t)(akof << 1);
    const uint32_t bko2 = (uint32_t)(bkof << 1);
    const uint32_t ahw_off = (uint32_t)(((wid ^ g) << 4) + 4 * cc);
    uint32_t wxb[2], whb[2];
#pragma unroll
    for (int np = 0; np < 2; ++np) {
        wxb[np] = sWX + (uint32_t)((n0 + np * 16 + bcol) * KXP + bkof) * 2;
        whb[np] = sWH + (uint32_t)(n0 + np * 16 + bcol) * 256;
    }

    float bias0[4], bias1[4];
#pragma unroll
    for (int nt = 0; nt < 4; ++nt) {
        bias0[nt] = sbias[n0 + nt * 8 + 2 * cc];
        bias1[nt] = sbias[n0 + nt * 8 + 2 * cc + 1];
    }

    uint32_t bxf[2][2][4];
#pragma unroll
    for (int ks = 0; ks < 2; ++ks)
#pragma unroll
        for (int np = 0; np < 2; ++np)
            ldm_x4(wxb[np] + (uint32_t)(ks * 32), bxf[ks][np]);

    float creg[MTILES][4];
#pragma unroll
    for (int mt = 0; mt < MTILES; ++mt)
#pragma unroll
        for (int nt = 0; nt < 4; ++nt) creg[mt][nt] = 0.0f;

    __syncthreads();

    {
        __half* AX = (__half*)(smem + OFF_AX0);
        for (int i = tid; i < AXE; i += LTHR) {
            int mm = i / DDIM, k = i - mm * DDIM;
            int n = blk * LNODES + mm;
            AX[mm * KXP + k] = __float2half_rn(n < NN ? x[n * (TT * DDIM) + 0 * DDIM + k] : 0.0f);
        }
    }

    for (int s = 0; s < TT; ++s) {
        __syncthreads();

        if (s + 1 < TT) {
            __half* AXN = (__half*)(smem + (((s + 1) & 1) ? OFF_AX1 : OFF_AX0));
            for (int i = tid; i < AXE; i += LTHR) {
                int mm = i / DDIM, k = i - mm * DDIM;
                int n = blk * LNODES + mm;
                AXN[mm * KXP + k] = __float2half_rn(n < NN ? x[n * (TT * DDIM) + (s + 1) * DDIM + k] : 0.0f);
            }
        }

        const bool last = (s == TT - 1);
        const uint32_t axb_r = (s & 1) ? axb1 : axb0;
        const uint32_t ahb_r = (s & 1) ? ahbase1 : ahbase0;
        char* AHWc = smem + ((s & 1) ? OFF_AH0 : OFF_AH1);

        auto epilogue = [&](int mt, float (&acc)[4][4]) {
#pragma unroll
            for (int hf = 0; hf < 2; ++hf) {
                const int row = mt * 16 + g + hf * 8;
                float hv[2];
#pragma unroll
                for (int b = 0; b < 2; ++b) {
                    const int z = hf * 2 + b;
                    float gi = acc[0][z], gf = acc[1][z];
                    float gg = acc[2][z], go = acc[3][z];
                    float cold = creg[mt][z];
                    float cn = sigt(gf) * cold + sigt(gi) * tanhapx(gg);
                    creg[mt][z] = cn;
                    hv[b] = sigt(go) * tanhapx(cn);
                }
                __half2 hvv = __floats2half2_rn(hv[0], hv[1]);
                *(__half2*)(AHWc + (uint32_t)row * 256 + ahw_off) = hvv;
                if (last) {
                    int node = blk * LNODES + row;
                    uint32_t byte = (uint32_t)(node >> 6) * 16384 + (uint32_t)(node & 63) * 256
                                  + (uint32_t)(((wid ^ (node & 7)) << 4) + 4 * cc);
                    *(__half2*)((char*)g_hh + byte) = hvv;
                }
            }
        };

#pragma unroll
        for (int p = 0; p < 5; ++p) {
            const int m0 = 2 * p;
            const bool has1 = (m0 + 1 < MTILES);

            float acc0[4][4], acc1[4][4];
#pragma unroll
            for (int nt = 0; nt < 4; ++nt) {
                acc0[nt][0] = bias0[nt]; acc0[nt][1] = bias1[nt];
                acc0[nt][2] = bias0[nt]; acc0[nt][3] = bias1[nt];
                acc1[nt][0] = bias0[nt]; acc1[nt][1] = bias1[nt];
                acc1[nt][2] = bias0[nt]; acc1[nt][3] = bias1[nt];
            }
#pragma unroll
            for (int ks = 0; ks < 2; ++ks) {
                uint32_t a[4];
                ldm_x4(axb_r + (uint32_t)(m0 * 16 * (KXP * 2) + ks * 32), a);
#pragma unroll
                for (int np = 0; np < 2; ++np) {
                    mma16816(acc0[2 * np],     a[0], a[1], a[2], a[3], bxf[ks][np][0], bxf[ks][np][1]);
                    mma16816(acc0[2 * np + 1], a[0], a[1], a[2], a[3], bxf[ks][np][2], bxf[ks][np][3]);
                }
                if (has1) {
                    uint32_t a1[4];
                    ldm_x4(axb_r + (uint32_t)((m0 + 1) * 16 * (KXP * 2) + ks * 32), a1);
#pragma unroll
                    for (int np = 0; np < 2; ++np) {
                        mma16816(acc1[2 * np],     a1[0], a1[1], a1[2], a1[3], bxf[ks][np][0], bxf[ks][np][1]);
                        mma16816(acc1[2 * np + 1], a1[0], a1[1], a1[2], a1[3], bxf[ks][np][2], bxf[ks][np][3]);
                    }
                }
            }
#pragma unroll
            for (int ks = 0; ks < 8; ++ks) {
                uint32_t b0[4], b1[4];
                ldm_x4(whb[0] + (((uint32_t)(ks * 32) + bko2) ^ xorv), b0);
                ldm_x4(whb[1] + (((uint32_t)(ks * 32) + bko2) ^ xorv), b1);
                uint32_t a[4];
                ldm_x4(ahb_r + (uint32_t)(m0 * 4096) + (((uint32_t)(ks * 32) + ako2) ^ xorv), a);
                mma16816(acc0[0], a[0], a[1], a[2], a[3], b0[0], b0[1]);
                mma16816(acc0[1], a[0], a[1], a[2], a[3], b0[2], b0[3]);
                mma16816(acc0[2], a[0], a[1], a[2], a[3], b1[0], b1[1]);
                mma16816(acc0[3], a[0], a[1], a[2], a[3], b1[2], b1[3]);
                if (has1) {
                    uint32_t a1[4];
                    ldm_x4(ahb_r + (uint32_t)((m0 + 1) * 4096) + (((uint32_t)(ks * 32) + ako2) ^ xorv), a1);
                    mma16816(acc1[0], a1[0], a1[1], a1[2], a1[3], b0[0], b0[1]);
                    mma16816(acc1[1], a1[0], a1[1], a1[2], a1[3], b0[2], b0[3]);
                    mma16816(acc1[2], a1[0], a1[1], a1[2], a1[3], b1[0], b1[1]);
                    mma16816(acc1[3], a1[0], a1[1], a1[2], a1[3], b1[2], b1[3]);
                }
            }

            epilogue(m0, acc0);
            if (has1) epilogue(m0 + 1, acc1);
        }
    }
}

// ---------------- W pre-conversion (runs hidden under LSTM) -------------------
__global__ void prep_w_kernel(const float* __restrict__ W, int layer) {
    int i = blockIdx.x * blockDim.x + threadIdx.x;
    if (i >= GGDIM * GGDIM) return;
    int n = i >> 7, k = i & 127;
    uint32_t byte = (uint32_t)(n * 256 + (((k >> 3) ^ (n & 7)) << 4) + ((k & 7) << 1));
    *(__half*)((char*)g_w16[layer] + byte) = __float2half_rn(W[k * GGDIM + n]);
}

// ---------------- CSR build ----------------------------------------------------
__global__ void csr_count_kernel(const int* __restrict__ ei) {
    int e = blockIdx.x * blockDim.x + threadIdx.x;
    if (e >= ETOT) return;
    int d = (e < EE) ? ei[EE + e] : (e - EE);
    atomicAdd(&g_cnt[d], 1);
}
__global__ __launch_bounds__(1024) void csr_scan_kernel() {
    __shared__ int swarp[32];
    const int t = threadIdx.x;
    const int lane = t & 31, wid = t >> 5;
    const int ITEMS = (NN + 1023) / 1024;
    const int base = t * ITEMS;

    int c[ITEMS];
    int total = 0;
#pragma unroll
    for (int i = 0; i < ITEMS; ++i) {
        int idx = base + i;
        c[i] = (idx < NN) ? g_cnt[idx] : 0;
        total += c[i];
        if (idx < NN) g_cnt[idx] = 0;
    }
    int incl = total;
#pragma unroll
    for (int o = 1; o < 32; o <<= 1) {
        int v = __shfl_up_sync(0xffffffffu, incl, o);
        if (lane >= o) incl += v;
    }
    if (lane == 31) swarp[wid] = incl;
    __syncthreads();
    if (wid == 0) {
        int w = swarp[lane];
        int wi = w;
#pragma unroll
        for (int o = 1; o < 32; o <<= 1) {
            int v = __shfl_up_sync(0xffffffffu, wi, o);
            if (lane >= o) wi += v;
        }
        swarp[lane] = wi - w;
    }
    __syncthreads();
    int run = swarp[wid] + (incl - total);
#pragma unroll
    for (int i = 0; i < ITEMS; ++i) {
        int idx = base + i;
        if (idx < NN) {
            g_row[idx] = run;
            g_cur[idx] = run;
            run += c[i];
        }
    }
    if (t == 1023) g_row[NN] = run;
}
__global__ void csr_scatter_kernel(const int* __restrict__ ei) {
    int e = blockIdx.x * blockDim.x + threadIdx.x;
    if (e >= ETOT) return;
    int s, d;
    if (e < EE) { s = ei[e]; d = ei[EE + e]; } else { s = e - EE; d = s; }
    int pos = atomicAdd(&g_cur[d], 1);
    g_csr[pos] = s;
}

// ---------------- fused GAT dense: xh = X@W (HMMA) + attn dots ----------------
__global__ __launch_bounds__(128) void gat_gemm_attn_kernel(
    const float* __restrict__ a_src, const float* __restrict__ a_dst, int layer)
{
    extern __shared__ char smem[];
    float* sas = (float*)(smem + GOFF_AS);
    float* sad = (float*)(smem + GOFF_AD);
    const uint32_t sA = (uint32_t)__cvta_generic_to_shared(smem + GOFF_A);
    const uint32_t sB = (uint32_t)__cvta_generic_to_shared(smem + GOFF_B);

    const int tid = threadIdx.x;
    const int n64 = blockIdx.x * 64;

    // A: straight 16KB copy (fp16, pre-swizzled 64-row tile)
    {
        const uint4* src = (layer == 0) ? &g_hh[(size_t)blockIdx.x * 1024]
                                        : &g_ft16[(size_t)blockIdx.x * 1024];
        uint4* dst = (uint4*)(smem + GOFF_A);
        for (int i = tid; i < 1024; i += 128) dst[i] = src[i];
    }
    // B: straight 32KB copy (fp16, pre-swizzled)
    {
        const uint4* src = g_w16[layer];
        uint4* dst = (uint4*)(smem + GOFF_B);
        for (int i = tid; i < 2048; i += 128) dst[i] = src[i];
    }
    if (tid < 128) { sas[tid] = a_src[tid]; sad[tid] = a_dst[tid]; }
    __syncthreads();

    const int wid  = tid >> 5;
    const int lane = tid & 31;
    const int g    = lane >> 2;
    const int cc   = lane & 3;
    const int sub = lane >> 3, rr = lane & 7;
    const int arow = (sub & 1) * 8 + rr;
    const int akof = (sub >> 1) * 8;
    const int bcol = rr + ((sub >> 1) * 8);
    const int bkof = (sub & 1) * 8;
    const uint32_t xorv = (uint32_t)(rr << 4);
    const uint32_t ako2 = (uint32_t)(akof << 1);
    const uint32_t bko2 = (uint32_t)(bkof << 1);
    const uint32_t arowb = sA + (uint32_t)(wid * 16 + arow) * 256;

    float acc[16][4];
#pragma unroll
    for (int q = 0; q < 16; ++q)
#pragma unroll
        for (int z = 0; z < 4; ++z) acc[q][z] = 0.0f;

#pragma unroll
    for (int ks = 0; ks < 8; ++ks) {
        uint32_t a[4];
        ldm_x4(arowb + (((uint32_t)(ks * 32) + ako2) ^ xorv), a);
#pragma unroll
        for (int np = 0; np < 8; ++np) {
            uint32_t b[4];
            ldm_x4(sB + (uint32_t)(np * 16 + bcol) * 256 + (((uint32_t)(ks * 32) + bko2) ^ xorv), b);
            mma16816(acc[2 * np],     a[0], a[1], a[2], a[3], b[0], b[1]);
            mma16816(acc[2 * np + 1], a[0], a[1], a[2], a[3], b[2], b[3]);
        }
    }

    const int gr0 = n64 + wid * 16 + g;
    const int gr1 = gr0 + 8;
#pragma unroll
    for (int np = 0; np < 8; ++np) {
        int c0 = np * 16 + 2 * cc, c1 = np * 16 + 8 + 2 * cc;
        if (gr0 < NN) {
            *(__half2*)((char*)g_xh16 + (size_t)gr0 * 256 + c0 * 2) =
                __floats2half2_rn(acc[2 * np][0], acc[2 * np][1]);
            *(__half2*)((char*)g_xh16 + (size_t)gr0 * 256 + c1 * 2) =
                __floats2half2_rn(acc[2 * np + 1][0], acc[2 * np + 1][1]);
        }
        if (gr1 < NN) {
            *(__half2*)((char*)g_xh16 + (size_t)gr1 * 256 + c0 * 2) =
                __floats2half2_rn(acc[2 * np][2], acc[2 * np][3]);
            *(__half2*)((char*)g_xh16 + (size_t)gr1 * 256 + c1 * 2) =
                __floats2half2_rn(acc[2 * np + 1][2], acc[2 * np + 1][3]);
        }
    }

    float rs0[4], rs1[4], rd0[4], rd1[4];
#pragma unroll
    for (int h = 0; h < 4; ++h) {
        float s0 = 0.0f, s1 = 0.0f, d0 = 0.0f, d1 = 0.0f;
#pragma unroll
        for (int tti = 0; tti < 4; ++tti) {
            int np = h * 2 + (tti >> 1);
            int ai = 2 * np + (tti & 1);
            int col = np * 16 + (tti & 1) * 8 + 2 * cc;
            float w0s = sas[col], w1s = sas[col + 1];
            float w0d = sad[col], w1d = sad[col + 1];
            s0 += acc[ai][0] * w0s + acc[ai][1] * w1s;
            s1 += acc[ai][2] * w0s + acc[ai][3] * w1s;
            d0 += acc[ai][0] * w0d + acc[ai][1] * w1d;
            d1 += acc[ai][2] * w0d + acc[ai][3] * w1d;
        }
        s0 += __shfl_xor_sync(0xffffffffu, s0, 1); s0 += __shfl_xor_sync(0xffffffffu, s0, 2);
        s1 += __shfl_xor_sync(0xffffffffu, s1, 1); s1 += __shfl_xor_sync(0xffffffffu, s1, 2);
        d0 += __shfl_xor_sync(0xffffffffu, d0, 1); d0 += __shfl_xor_sync(0xffffffffu, d0, 2);
        d1 += __shfl_xor_sync(0xffffffffu, d1, 1); d1 += __shfl_xor_sync(0xffffffffu, d1, 2);
        rs0[h] = s0; rs1[h] = s1; rd0[h] = d0; rd1[h] = d1;
    }
    if (gr0 < NN) { g_asr[gr0 * 4 + cc] = rs0[cc]; g_adt[gr0 * 4 + cc] = rd0[cc]; }
    if (gr1 < NN) { g_asr[gr1 * 4 + cc] = rs1[cc]; g_adt[gr1 * 4 + cc] = rd1[cc]; }
}

// -------- single-pass softmax-aggregate + bias + ELU (+ optional head) --------
__global__ __launch_bounds__(256) void gat_agg_kernel(
    const float* __restrict__ bias, const float* __restrict__ Wh,
    const float* __restrict__ bh, float* __restrict__ out, int last)
{
    const int d    = (blockIdx.x * 256 + threadIdx.x) >> 5;
    const int lane = threadIdx.x & 31;
    if (d >= NN) return;
    const int start = g_row[d], end = g_row[d + 1];

    const int head = lane >> 3;
    const float adt_h = g_adt[d * 4 + head];

    float den = 0.0f;
    float4 acc = make_float4(0.0f, 0.0f, 0.0f, 0.0f);
#pragma unroll 4
    for (int idx = start; idx < end; ++idx) {
        int s = g_csr[idx];
        float e = __expf(lrelu(g_asr[s * 4 + head] + adt_h));
        uint2 xv = *(const uint2*)((const char*)g_xh16 + (size_t)s * 256 + lane * 8);
        float2 f0 = __half22float2(*(__half2*)&xv.x);
        float2 f1 = __half22float2(*(__half2*)&xv.y);
        den += e;
        acc.x = fmaf(e, f0.x, acc.x);
        acc.y = fmaf(e, f0.y, acc.y);
        acc.z = fmaf(e, f1.x, acc.z);
        acc.w = fmaf(e, f1.y, acc.w);
    }
    const float inv_den = 1.0f / (den + 1e-16f);

    const float4 bv = *(const float4*)&bias[lane * 4];
    float4 outv;
    float v;
    v = fmaf(acc.x, inv_den, bv.x); outv.x = v > 0.0f ? v : (__expf(v) - 1.0f);
    v = fmaf(acc.y, inv_den, bv.y); outv.y = v > 0.0f ? v : (__expf(v) - 1.0f);
    v = fmaf(acc.z, inv_den, bv.z); outv.z = v > 0.0f ? v : (__expf(v) - 1.0f);
    v = fmaf(acc.w, inv_den, bv.w); outv.w = v > 0.0f ? v : (__expf(v) - 1.0f);

    if (!last) {
        // write feat fp16 into the pre-swizzled tile layout
        int r = d & 63, ch = lane * 4;
        uint32_t byte = (uint32_t)(d >> 6) * 16384 + (uint32_t)r * 256
                      + (uint32_t)((((ch >> 3) ^ (r & 7)) << 4) + ((ch & 7) << 1));
        __half2 o0 = __floats2half2_rn(outv.x, outv.y);
        __half2 o1 = __floats2half2_rn(outv.z, outv.w);
        uint2 pack;
        pack.x = *(uint32_t*)&o0;
        pack.y = *(uint32_t*)&o1;
        *(uint2*)((char*)g_ft16 + byte) = pack;
    } else {
        int ch = lane * 4;
        float p0 = outv.x * Wh[2 * ch + 0] + outv.y * Wh[2 * ch + 2]
                 + outv.z * Wh[2 * ch + 4] + outv.w * Wh[2 * ch + 6];
        float p1 = outv.x * Wh[2 * ch + 1] + outv.y * Wh[2 * ch + 3]
                 + outv.z * Wh[2 * ch + 5] + outv.w * Wh[2 * ch + 7];
#pragma unroll
        for (int off = 16; off > 0; off >>= 1) {
            p0 += __shfl_xor_sync(0xffffffffu, p0, off);
            p1 += __shfl_xor_sync(0xffffffffu, p1, off);
        }
        if (lane == 0) {
            out[2 * d + 0] = p0 + bh[0];
            out[2 * d + 1] = p1 + bh[1];
        }
    }
}

// ---------------- launch --------------------------------------------------------
extern "C" void kernel_launch(void* const* d_in, const int* in_sizes, int n_in,
                              void* d_out, int out_size) {
    const float* x_win  = (const float*)d_in[0];
    const int*   ei     = (const int*)  d_in[1];
    const float* Wih    = (const float*)d_in[2];
    const float* Whh    = (const float*)d_in[3];
    const float* bih    = (const float*)d_in[4];
    const float* bhh    = (const float*)d_in[5];
    const float* W1     = (const float*)d_in[6];
    const float* asrc1  = (const float*)d_in[7];
    const float* adst1  = (const float*)d_in[8];
    const float* b1     = (const float*)d_in[9];
    const float* W2     = (const float*)d_in[10];
    const float* asrc2  = (const float*)d_in[11];
    const float* adst2  = (const float*)d_in[12];
    const float* b2     = (const float*)d_in[13];
    const float* Wh     = (const float*)d_in[14];
    const float* bh     = (const float*)d_in[15];
    float* out = (float*)d_out;

    static cudaStream_t s_aux = nullptr;
    static cudaEvent_t  ev_fork = nullptr, ev_join = nullptr;
    static bool attr_done = false;
    if (!attr_done) {
        cudaFuncSetAttribute(lstm_all_kernel,
                             cudaFuncAttributeMaxDynamicSharedMemorySize, SMEM_TOTAL);
        cudaFuncSetAttribute(gat_gemm_attn_kernel,
                             cudaFuncAttributeMaxDynamicSharedMemorySize, GSMEM);
        cudaStreamCreateWithFlags(&s_aux, cudaStreamNonBlocking);
        cudaEventCreateWithFlags(&ev_fork, cudaEventDisableTiming);
        cudaEventCreateWithFlags(&ev_join, cudaEventDisableTiming);
        attr_done = true;
    }

    // fork: CSR build + W conversion run concurrently with the LSTM
    cudaEventRecord(ev_fork, 0);
    cudaStreamWaitEvent(s_aux, ev_fork, 0);

    lstm_all_kernel<<<LGRID, LTHR, SMEM_TOTAL>>>(x_win, Wih, Whh, bih, bhh);

    csr_count_kernel<<<(ETOT + 255) / 256, 256, 0, s_aux>>>(ei);
    csr_scan_kernel<<<1, 1024, 0, s_aux>>>();
    csr_scatter_kernel<<<(ETOT + 255) / 256, 256, 0, s_aux>>>(ei);
    prep_w_kernel<<<64, 256, 0, s_aux>>>(W1, 0);
    prep_w_kernel<<<64, 256, 0, s_aux>>>(W2, 1);
    cudaEventRecord(ev_join, s_aux);
    cudaStreamWaitEvent(0, ev_join, 0);

    for (int layer = 0; layer < 2; layer++) {
        const float* asrc = layer ? asrc2 : asrc1;
        const float* adst = layer ? adst2 : adst1;
        const float* bb   = layer ? b2    : b1;

        gat_gemm_attn_kernel<<<NT64, 128, GSMEM>>>(asrc, adst, layer);
        gat_agg_kernel<<<(NN * 32 + 255) / 256, 256>>>(bb, Wh, bh, out, layer);
    }
}